// round 2
// baseline (speedup 1.0000x reference)
#include <cuda_runtime.h>
#include <cstdint>

#define NFEAT 64
#define NHID  128
#define MAXN  65536
#define MAXE  1048576

// ---------------- device scratch (allocation-free contract) ----------------
__device__ __align__(256) float g_h[MAXN * NFEAT];      // x + agg
__device__ __align__(256) float g_h1[MAXN * NHID];      // relu(SN-lin1) output
__device__ __align__(256) float g_stats[256];           // [0:128) sum, [128:256) sumsq
__device__ __align__(256) float g_inv_sigma[2];
__device__ __align__(256) float g_W2eff[NHID * NHID];
__device__ __align__(256) float g_b2eff[NHID];
__device__ int g_idx_mode;                              // 0 = int64 edges, 1 = int32 edges

// ---------------- edge dtype probe ----------------
__global__ void detect_kernel(const long long* __restrict__ ei64, int N) {
    // True int64 indices are all in [0, N). int32 data reinterpreted as int64
    // has a nonzero high word with prob ~1-2^-16 per entry.
    int mode = 0;
    for (int e = 0; e < 64; e++) {
        long long v = ei64[e];
        if (v < 0 || v >= (long long)N) { mode = 1; break; }
    }
    g_idx_mode = mode;
}

// ---------------- spectral norm (tiny) ----------------
__device__ float block_reduce_sum256(float v, float* sred) {
    int t = threadIdx.x;
    sred[t] = v;
    __syncthreads();
    for (int s = 128; s > 0; s >>= 1) {
        if (t < s) sred[t] += sred[t + s];
        __syncthreads();
    }
    float r = sred[0];
    __syncthreads();
    return r;
}

__device__ void compute_inv_sigma(const float* __restrict__ W, const float* __restrict__ u,
                                  int n, int m, float* out, float* sv, float* sred) {
    int t = threadIdx.x;
    float vt = 0.f;
    if (t < m) {
        for (int i = 0; i < n; i++) vt += W[i * m + t] * u[i];
    }
    float s = block_reduce_sum256((t < m) ? vt * vt : 0.f, sred);
    if (t < m) sv[t] = vt / (sqrtf(s) + 1e-12f);
    __syncthreads();
    float wv = 0.f;
    if (t < n) {
        for (int k = 0; k < m; k++) wv += W[t * m + k] * sv[k];
    }
    float s2 = block_reduce_sum256((t < n) ? wv * wv : 0.f, sred);
    if (t == 0) {
        float sig = s2 / (sqrtf(s2) + 1e-12f);
        *out = 1.f / sig;
    }
    __syncthreads();
}

__global__ void prep_kernel(const float* __restrict__ W1, const float* __restrict__ u1,
                            const float* __restrict__ W2, const float* __restrict__ u2,
                            float* __restrict__ inv_sigma) {
    __shared__ float sv[128];
    __shared__ float sred[256];
    compute_inv_sigma(W1, u1, NHID, NFEAT, &inv_sigma[0], sv, sred);
    compute_inv_sigma(W2, u2, NHID, NHID, &inv_sigma[1], sv, sred);
}

// ---------------- init: h = x, stats = 0 ----------------
__global__ void init_kernel(const float4* __restrict__ x4, float4* __restrict__ h4,
                            float* __restrict__ stats, int n4) {
    int i = blockIdx.x * blockDim.x + threadIdx.x;
    if (i < n4) h4[i] = x4[i];
    if (blockIdx.x == 0 && threadIdx.x < 256) stats[threadIdx.x] = 0.f;
}

// ---------------- scatter: h[dst] += x[src], vectorized red ----------------
__global__ void scatter_kernel(const void* __restrict__ eiv,
                               const float4* __restrict__ x4,
                               float4* __restrict__ h4, int E, int N) {
    int i = blockIdx.x * blockDim.x + threadIdx.x;
    if (i >= E * 16) return;
    int e = i >> 4;
    int c = i & 15;
    long long s, d;
    if (g_idx_mode == 0) {
        const long long* ei = (const long long*)eiv;
        s = ei[e];
        d = ei[E + e];
    } else {
        const int* ei = (const int*)eiv;
        s = ei[e];
        d = ei[E + e];
    }
    if (s < 0 || s >= N || d < 0 || d >= N) return;  // safety: never IMA
    float4 v = __ldg(&x4[s * 16 + c]);
    float4* p = h4 + d * 16 + c;
    asm volatile("red.global.add.v4.f32 [%0], {%1,%2,%3,%4};"
                 :: "l"(p), "f"(v.x), "f"(v.y), "f"(v.z), "f"(v.w)
                 : "memory");
}

// ---------------- fused GEMM: out[r][f] = act( in[r][:] . W[f][:] * scale + b[f] ) ----
// Block: 512 threads, 64 rows/block. Thread (f4 = tid&31, rw = tid>>5) computes
// 4 rows {rw, rw+16, rw+32, rw+48} x 4 features {f4*4 .. f4*4+3}.
template <int K, bool RELU, bool SCALE>
__global__ void __launch_bounds__(512) gemm_kernel(
    const float* __restrict__ in, const float* __restrict__ W,
    const float* __restrict__ bias, const float* __restrict__ scale_ptr,
    float* __restrict__ out) {
    constexpr int XS = K + 4;
    extern __shared__ float sm[];
    float* sX  = sm;                 // 64*XS
    float* sWt = sm + 64 * XS;       // K*128
    float* sB  = sWt + K * 128;      // 128

    const int tid = threadIdx.x;
    float scale = 1.f;
    if (SCALE) scale = *scale_ptr;

    for (int idx = tid; idx < 128 * K; idx += 512) {
        int f = idx / K, k = idx - f * K;
        sWt[k * 128 + f] = W[idx] * scale;
    }
    if (tid < 128) sB[tid] = bias[tid];

    const int row0 = blockIdx.x * 64;
    const float4* in4 = reinterpret_cast<const float4*>(in) + (size_t)row0 * (K / 4);
    for (int q = tid; q < 64 * (K / 4); q += 512) {
        int r = q / (K / 4), c = q - r * (K / 4);
        *reinterpret_cast<float4*>(&sX[r * XS + c * 4]) = in4[q];
    }
    __syncthreads();

    const int f4 = tid & 31;
    const int rw = tid >> 5;

    float acc[4][4];
#pragma unroll
    for (int i = 0; i < 4; i++)
#pragma unroll
        for (int j = 0; j < 4; j++) acc[i][j] = sB[f4 * 4 + j];

#pragma unroll 4
    for (int k4 = 0; k4 < K / 4; k4++) {
        float4 xv[4];
#pragma unroll
        for (int i = 0; i < 4; i++)
            xv[i] = *reinterpret_cast<const float4*>(&sX[(rw + 16 * i) * XS + k4 * 4]);
#pragma unroll
        for (int kk = 0; kk < 4; kk++) {
            float4 w = *reinterpret_cast<const float4*>(&sWt[(k4 * 4 + kk) * 128 + f4 * 4]);
#pragma unroll
            for (int i = 0; i < 4; i++) {
                float xs = reinterpret_cast<const float*>(&xv[i])[kk];
                acc[i][0] += xs * w.x;
                acc[i][1] += xs * w.y;
                acc[i][2] += xs * w.z;
                acc[i][3] += xs * w.w;
            }
        }
    }

#pragma unroll
    for (int i = 0; i < 4; i++) {
        float4 o;
        o.x = acc[i][0]; o.y = acc[i][1]; o.z = acc[i][2]; o.w = acc[i][3];
        if (RELU) {
            o.x = fmaxf(o.x, 0.f); o.y = fmaxf(o.y, 0.f);
            o.z = fmaxf(o.z, 0.f); o.w = fmaxf(o.w, 0.f);
        }
        reinterpret_cast<float4*>(out)[(size_t)(row0 + rw + 16 * i) * 32 + f4] = o;
    }
}

// ---------------- column stats of h1 (post-relu) ----------------
__global__ void stats_kernel(const float* __restrict__ h1, float* __restrict__ stats, int N) {
    int f = threadIdx.x & 127;
    int sub = threadIdx.x >> 7;
    float s = 0.f, ss = 0.f;
    for (int row = blockIdx.x * 2 + sub; row < N; row += gridDim.x * 2) {
        float v = h1[(size_t)row * 128 + f];
        s += v;
        ss += v * v;
    }
    __shared__ float sh[256];
    sh[threadIdx.x] = s;
    __syncthreads();
    float stot = 0.f;
    if (sub == 0) stot = s + sh[128 + f];
    __syncthreads();
    sh[threadIdx.x] = ss;
    __syncthreads();
    if (sub == 0) {
        float sstot = ss + sh[128 + f];
        atomicAdd(&stats[f], stot);
        atomicAdd(&stats[128 + f], sstot);
    }
}

// ---------------- fold BN + SN into effective W2/b2 ----------------
__global__ void finalize_kernel(const float* __restrict__ W2, const float* __restrict__ b2,
                                const float* __restrict__ gamma, const float* __restrict__ beta,
                                const float* __restrict__ stats, const float* __restrict__ inv_sigma,
                                float* __restrict__ W2eff, float* __restrict__ b2eff, int N) {
    __shared__ float a[128], c[128];
    int t = threadIdx.x;
    float invN = 1.f / (float)N;
    float mean = stats[t] * invN;
    float var = stats[128 + t] * invN - mean * mean;
    float af = gamma[t] * rsqrtf(var + 1e-5f);
    a[t] = af;
    c[t] = beta[t] - mean * af;
    __syncthreads();
    float is2 = inv_sigma[1];
    float bacc = 0.f;
    for (int f = 0; f < 128; f++) {
        float w = W2[t * 128 + f] * is2;
        W2eff[t * 128 + f] = w * a[f];
        bacc += c[f] * w;
    }
    b2eff[t] = b2[t] + bacc;
}

// ---------------- launch ----------------
extern "C" void kernel_launch(void* const* d_in, const int* in_sizes, int n_in,
                              void* d_out, int out_size) {
    const float* x        = (const float*)d_in[0];
    const void*  ei       = d_in[1];
    const float* W1       = (const float*)d_in[2];
    const float* b1       = (const float*)d_in[3];
    const float* u1       = (const float*)d_in[4];
    const float* gamma    = (const float*)d_in[5];
    const float* beta     = (const float*)d_in[6];
    const float* W2       = (const float*)d_in[7];
    const float* b2       = (const float*)d_in[8];
    const float* u2       = (const float*)d_in[9];

    int N = in_sizes[0] / NFEAT;
    int E = in_sizes[1] / 2;

    float *pH, *pH1, *pStats, *pInv, *pW2eff, *pB2eff;
    cudaGetSymbolAddress((void**)&pH, g_h);
    cudaGetSymbolAddress((void**)&pH1, g_h1);
    cudaGetSymbolAddress((void**)&pStats, g_stats);
    cudaGetSymbolAddress((void**)&pInv, g_inv_sigma);
    cudaGetSymbolAddress((void**)&pW2eff, g_W2eff);
    cudaGetSymbolAddress((void**)&pB2eff, g_b2eff);

    // 0) probe edge index dtype (int64 vs int32), device-side
    detect_kernel<<<1, 1>>>((const long long*)ei, N);

    // 1) spectral norms
    prep_kernel<<<1, 256>>>(W1, u1, W2, u2, pInv);

    // 2) h = x ; stats = 0
    int n4 = N * NFEAT / 4;
    init_kernel<<<(n4 + 255) / 256, 256>>>((const float4*)x, (float4*)pH, pStats, n4);

    // 3) scatter-add h[dst] += x[src]
    int items = E * 16;
    scatter_kernel<<<(items + 255) / 256, 256>>>(ei, (const float4*)x, (float4*)pH, E, N);

    // 4) h1 = relu(h @ (W1/sigma1)^T + b1)
    int smem1 = (64 * (NFEAT + 4) + NFEAT * 128 + 128) * (int)sizeof(float);
    cudaFuncSetAttribute(gemm_kernel<NFEAT, true, true>,
                         cudaFuncAttributeMaxDynamicSharedMemorySize, smem1);
    gemm_kernel<NFEAT, true, true><<<N / 64, 512, smem1>>>(pH, W1, b1, pInv, pH1);

    // 5) BN stats
    stats_kernel<<<1024, 256>>>(pH1, pStats, N);

    // 6) fold BN+SN into W2eff/b2eff
    finalize_kernel<<<1, 128>>>(W2, b2, gamma, beta, pStats, pInv, pW2eff, pB2eff, N);

    // 7) out = h1 @ W2eff^T + b2eff
    int smem2 = (64 * (NHID + 4) + NHID * 128 + 128) * (int)sizeof(float);
    cudaFuncSetAttribute(gemm_kernel<NHID, false, false>,
                         cudaFuncAttributeMaxDynamicSharedMemorySize, smem2);
    gemm_kernel<NHID, false, false><<<N / 64, 512, smem2>>>(pH1, pW2eff, pB2eff, nullptr,
                                                            (float*)d_out);
}

// round 3
// speedup vs baseline: 1.0441x; 1.0441x over previous
#include <cuda_runtime.h>
#include <cstdint>

#define NFEAT 64
#define NHID  128
#define MAXN  65536
#define MAXE  1048576

typedef unsigned long long ull;

// ---------------- device scratch (allocation-free contract) ----------------
__device__ __align__(256) float g_h[MAXN * NFEAT];      // x + agg
__device__ __align__(256) float g_h1[MAXN * NHID];      // relu(SN-lin1) output
__device__ __align__(256) float g_stats[256];           // [0:128) sum, [128:256) sumsq
__device__ __align__(256) float g_inv_sigma[2];
__device__ __align__(256) float g_W2eff[NHID * NHID];
__device__ __align__(256) float g_b2eff[NHID];
__device__ int g_idx_mode;                              // 0 = int64 edges, 1 = int32 edges

// ---------------- packed fp32x2 fma (SASS FFMA2, exact fp32) ----------------
__device__ __forceinline__ ull ffma2(ull a, ull b, ull c) {
    ull d;
    asm("fma.rn.f32x2 %0, %1, %2, %3;" : "=l"(d) : "l"(a), "l"(b), "l"(c));
    return d;
}

// ---------------- edge dtype probe + stats zero ----------------
__global__ void detect_kernel(const long long* __restrict__ ei64, int N,
                              float* __restrict__ stats) {
    int t = threadIdx.x;  // 64 threads
    long long v = ei64[t];
    unsigned bad = __ballot_sync(0xffffffffu, (v < 0 || v >= (long long)N));
    __shared__ unsigned sb[2];
    if ((t & 31) == 0) sb[t >> 5] = bad;
    __syncthreads();
    if (t == 0) g_idx_mode = (sb[0] | sb[1]) ? 1 : 0;
    stats[t] = 0.f; stats[t + 64] = 0.f; stats[t + 128] = 0.f; stats[t + 192] = 0.f;
}

// ---------------- spectral norm (tiny) ----------------
__device__ float block_reduce_sum256(float v, float* sred) {
    int t = threadIdx.x;
    sred[t] = v;
    __syncthreads();
    for (int s = 128; s > 0; s >>= 1) {
        if (t < s) sred[t] += sred[t + s];
        __syncthreads();
    }
    float r = sred[0];
    __syncthreads();
    return r;
}

__device__ void compute_inv_sigma(const float* __restrict__ W, const float* __restrict__ u,
                                  int n, int m, float* out, float* sv, float* sred) {
    int t = threadIdx.x;
    float vt = 0.f;
    if (t < m) {
        for (int i = 0; i < n; i++) vt += W[i * m + t] * u[i];
    }
    float s = block_reduce_sum256((t < m) ? vt * vt : 0.f, sred);
    if (t < m) sv[t] = vt / (sqrtf(s) + 1e-12f);
    __syncthreads();
    float wv = 0.f;
    if (t < n) {
        for (int k = 0; k < m; k++) wv += W[t * m + k] * sv[k];
    }
    float s2 = block_reduce_sum256((t < n) ? wv * wv : 0.f, sred);
    if (t == 0) {
        float sig = s2 / (sqrtf(s2) + 1e-12f);
        *out = 1.f / sig;
    }
    __syncthreads();
}

__global__ void prep_kernel(const float* __restrict__ W1, const float* __restrict__ u1,
                            const float* __restrict__ W2, const float* __restrict__ u2,
                            float* __restrict__ inv_sigma) {
    __shared__ float sv[128];
    __shared__ float sred[256];
    compute_inv_sigma(W1, u1, NHID, NFEAT, &inv_sigma[0], sv, sred);
    compute_inv_sigma(W2, u2, NHID, NHID, &inv_sigma[1], sv, sred);
}

// ---------------- init: h = x ----------------
__global__ void init_kernel(const float4* __restrict__ x4, float4* __restrict__ h4, int n4) {
    int i = blockIdx.x * blockDim.x + threadIdx.x;
    if (i < n4) h4[i] = x4[i];
}

// ---------------- scatter: h[dst] += x[src], vectorized red, 8 thr/edge ----------------
__global__ void scatter_kernel(const void* __restrict__ eiv,
                               const float4* __restrict__ x4,
                               float4* __restrict__ h4, int E, int N) {
    int i = blockIdx.x * blockDim.x + threadIdx.x;
    if (i >= E * 8) return;
    int e = i >> 3;
    int c = i & 7;
    long long s, d;
    if (g_idx_mode == 0) {
        const long long* ei = (const long long*)eiv;
        s = ei[e];
        d = ei[E + e];
    } else {
        const int* ei = (const int*)eiv;
        s = ei[e];
        d = ei[E + e];
    }
    if ((ull)s >= (ull)N || (ull)d >= (ull)N) return;  // safety: never IMA
    const float4* xs = x4 + s * 16 + c;
    float4 v0 = __ldg(xs);
    float4 v1 = __ldg(xs + 8);
    float4* p = h4 + d * 16 + c;
    asm volatile("red.global.add.v4.f32 [%0], {%1,%2,%3,%4};"
                 :: "l"(p), "f"(v0.x), "f"(v0.y), "f"(v0.z), "f"(v0.w) : "memory");
    asm volatile("red.global.add.v4.f32 [%0], {%1,%2,%3,%4};"
                 :: "l"(p + 8), "f"(v1.x), "f"(v1.y), "f"(v1.z), "f"(v1.w) : "memory");
}

// ---------------- FFMA2 GEMM: out[r][f] = act( in[r][:] . W[f][:]*scale + b[f] ) ----
// Tile: 128 rows x 128 feats, 256 threads, thread = 8 rows x 8 feats.
// smem: sXd = x duplicated as (x,x) 8B pairs -> free packed operand via LDS.128
//       sWt = transposed weights -> adjacent-feature pairs free via LDS.128
template <int K, bool RELU, bool SCALE>
__global__ void __launch_bounds__(256) gemm_kernel(
    const float* __restrict__ in, const float* __restrict__ W,
    const float* __restrict__ bias, const float* __restrict__ scale_ptr,
    float* __restrict__ out) {
    extern __shared__ float sm[];
    float* sXd = sm;                       // 128*K*2 floats (dup pairs)
    float* sWt = sm + 128 * K * 2;         // K*128 floats
    float* sB  = sWt + K * 128;            // 128 floats

    const int tid = threadIdx.x;
    const float scale = SCALE ? *scale_ptr : 1.f;

    // W[f][k] -> sWt[k][f], scaled (coalesced reads)
    for (int idx = tid; idx < 128 * K; idx += 256) {
        int f = idx / K, k = idx - f * K;
        sWt[k * 128 + f] = W[idx] * scale;
    }
    if (tid < 128) sB[tid] = bias[tid];

    // X tile -> duplicated pairs
    const int row0 = blockIdx.x * 128;
    const float4* in4 = reinterpret_cast<const float4*>(in) + (size_t)row0 * (K / 4);
    for (int q = tid; q < 128 * (K / 4); q += 256) {
        int r = q / (K / 4), c = q - r * (K / 4);
        float4 v = in4[q];
        float4* dst = reinterpret_cast<float4*>(sXd + (size_t)(r * K + 4 * c) * 2);
        dst[0] = make_float4(v.x, v.x, v.y, v.y);
        dst[1] = make_float4(v.z, v.z, v.w, v.w);
    }
    __syncthreads();

    const int fg = tid & 15;   // feats fg*8 .. fg*8+7
    const int rg = tid >> 4;   // rows rg*8 .. rg*8+7

    ull acc[8][4];
    {
        float4 b0 = *reinterpret_cast<const float4*>(&sB[fg * 8]);
        float4 b1 = *reinterpret_cast<const float4*>(&sB[fg * 8 + 4]);
        ull p0 = reinterpret_cast<const ull*>(&b0)[0];
        ull p1 = reinterpret_cast<const ull*>(&b0)[1];
        ull p2 = reinterpret_cast<const ull*>(&b1)[0];
        ull p3 = reinterpret_cast<const ull*>(&b1)[1];
#pragma unroll
        for (int j = 0; j < 8; j++) {
            acc[j][0] = p0; acc[j][1] = p1; acc[j][2] = p2; acc[j][3] = p3;
        }
    }

    const float* xrow = sXd + (size_t)(rg * 8) * (K * 2);

#pragma unroll 2
    for (int k2 = 0; k2 < K / 2; k2++) {
        // weights for k = 2*k2 (A) and 2*k2+1 (B): natural feature pairs
        float4 wa0 = *reinterpret_cast<const float4*>(&sWt[(2 * k2) * 128 + fg * 8]);
        float4 wa1 = *reinterpret_cast<const float4*>(&sWt[(2 * k2) * 128 + fg * 8 + 4]);
        float4 wb0 = *reinterpret_cast<const float4*>(&sWt[(2 * k2 + 1) * 128 + fg * 8]);
        float4 wb1 = *reinterpret_cast<const float4*>(&sWt[(2 * k2 + 1) * 128 + fg * 8 + 4]);
        ull wA0 = reinterpret_cast<const ull*>(&wa0)[0];
        ull wA1 = reinterpret_cast<const ull*>(&wa0)[1];
        ull wA2 = reinterpret_cast<const ull*>(&wa1)[0];
        ull wA3 = reinterpret_cast<const ull*>(&wa1)[1];
        ull wB0 = reinterpret_cast<const ull*>(&wb0)[0];
        ull wB1 = reinterpret_cast<const ull*>(&wb0)[1];
        ull wB2 = reinterpret_cast<const ull*>(&wb1)[0];
        ull wB3 = reinterpret_cast<const ull*>(&wb1)[1];
#pragma unroll
        for (int j = 0; j < 8; j++) {
            // (x_k dup, x_{k+1} dup) for row j
            float4 xp = *reinterpret_cast<const float4*>(&xrow[(size_t)j * (K * 2) + k2 * 4]);
            ull xlo = reinterpret_cast<const ull*>(&xp)[0];
            ull xhi = reinterpret_cast<const ull*>(&xp)[1];
            acc[j][0] = ffma2(xlo, wA0, acc[j][0]);
            acc[j][1] = ffma2(xlo, wA1, acc[j][1]);
            acc[j][2] = ffma2(xlo, wA2, acc[j][2]);
            acc[j][3] = ffma2(xlo, wA3, acc[j][3]);
            acc[j][0] = ffma2(xhi, wB0, acc[j][0]);
            acc[j][1] = ffma2(xhi, wB1, acc[j][1]);
            acc[j][2] = ffma2(xhi, wB2, acc[j][2]);
            acc[j][3] = ffma2(xhi, wB3, acc[j][3]);
        }
    }

#pragma unroll
    for (int j = 0; j < 8; j++) {
        float4 o0, o1;
        reinterpret_cast<ull*>(&o0)[0] = acc[j][0];
        reinterpret_cast<ull*>(&o0)[1] = acc[j][1];
        reinterpret_cast<ull*>(&o1)[0] = acc[j][2];
        reinterpret_cast<ull*>(&o1)[1] = acc[j][3];
        if (RELU) {
            o0.x = fmaxf(o0.x, 0.f); o0.y = fmaxf(o0.y, 0.f);
            o0.z = fmaxf(o0.z, 0.f); o0.w = fmaxf(o0.w, 0.f);
            o1.x = fmaxf(o1.x, 0.f); o1.y = fmaxf(o1.y, 0.f);
            o1.z = fmaxf(o1.z, 0.f); o1.w = fmaxf(o1.w, 0.f);
        }
        int row = row0 + rg * 8 + j;
        float4* op = reinterpret_cast<float4*>(out) + (size_t)row * 32 + fg * 2;
        op[0] = o0;
        op[1] = o1;
    }
}

// ---------------- column stats of h1 (post-relu) ----------------
__global__ void stats_kernel(const float* __restrict__ h1, float* __restrict__ stats, int N) {
    int f = threadIdx.x & 127;
    int sub = threadIdx.x >> 7;
    float s = 0.f, ss = 0.f;
    for (int row = blockIdx.x * 2 + sub; row < N; row += gridDim.x * 2) {
        float v = h1[(size_t)row * 128 + f];
        s += v;
        ss += v * v;
    }
    __shared__ float sh[256];
    sh[threadIdx.x] = s;
    __syncthreads();
    float stot = 0.f;
    if (sub == 0) stot = s + sh[128 + f];
    __syncthreads();
    sh[threadIdx.x] = ss;
    __syncthreads();
    if (sub == 0) {
        float sstot = ss + sh[128 + f];
        atomicAdd(&stats[f], stot);
        atomicAdd(&stats[128 + f], sstot);
    }
}

// ---------------- fold BN + SN into effective W2/b2 ----------------
__global__ void finalize_kernel(const float* __restrict__ W2, const float* __restrict__ b2,
                                const float* __restrict__ gamma, const float* __restrict__ beta,
                                const float* __restrict__ stats, const float* __restrict__ inv_sigma,
                                float* __restrict__ W2eff, float* __restrict__ b2eff, int N) {
    __shared__ float a[128], c[128];
    int t = threadIdx.x;
    float invN = 1.f / (float)N;
    float mean = stats[t] * invN;
    float var = stats[128 + t] * invN - mean * mean;
    float af = gamma[t] * rsqrtf(var + 1e-5f);
    a[t] = af;
    c[t] = beta[t] - mean * af;
    __syncthreads();
    float is2 = inv_sigma[1];
    float bacc = 0.f;
    for (int f = 0; f < 128; f++) {
        float w = W2[t * 128 + f] * is2;
        W2eff[t * 128 + f] = w * a[f];
        bacc += c[f] * w;
    }
    b2eff[t] = b2[t] + bacc;
}

// ---------------- launch ----------------
extern "C" void kernel_launch(void* const* d_in, const int* in_sizes, int n_in,
                              void* d_out, int out_size) {
    const float* x        = (const float*)d_in[0];
    const void*  ei       = d_in[1];
    const float* W1       = (const float*)d_in[2];
    const float* b1       = (const float*)d_in[3];
    const float* u1       = (const float*)d_in[4];
    const float* gamma    = (const float*)d_in[5];
    const float* beta     = (const float*)d_in[6];
    const float* W2       = (const float*)d_in[7];
    const float* b2       = (const float*)d_in[8];
    const float* u2       = (const float*)d_in[9];

    int N = in_sizes[0] / NFEAT;
    int E = in_sizes[1] / 2;

    float *pH, *pH1, *pStats, *pInv, *pW2eff, *pB2eff;
    cudaGetSymbolAddress((void**)&pH, g_h);
    cudaGetSymbolAddress((void**)&pH1, g_h1);
    cudaGetSymbolAddress((void**)&pStats, g_stats);
    cudaGetSymbolAddress((void**)&pInv, g_inv_sigma);
    cudaGetSymbolAddress((void**)&pW2eff, g_W2eff);
    cudaGetSymbolAddress((void**)&pB2eff, g_b2eff);

    // 0) probe edge index dtype (int64 vs int32) + zero stats
    detect_kernel<<<1, 64>>>((const long long*)ei, N, pStats);

    // 1) spectral norms
    prep_kernel<<<1, 256>>>(W1, u1, W2, u2, pInv);

    // 2) h = x
    int n4 = N * NFEAT / 4;
    init_kernel<<<(n4 + 255) / 256, 256>>>((const float4*)x, (float4*)pH, n4);

    // 3) scatter-add h[dst] += x[src]
    int items = E * 8;
    scatter_kernel<<<(items + 255) / 256, 256>>>(ei, (const float4*)x, (float4*)pH, E, N);

    // 4) h1 = relu(h @ (W1/sigma1)^T + b1)
    int smem1 = (128 * NFEAT * 2 + NFEAT * 128 + 128) * (int)sizeof(float);
    cudaFuncSetAttribute(gemm_kernel<NFEAT, true, true>,
                         cudaFuncAttributeMaxDynamicSharedMemorySize, smem1);
    gemm_kernel<NFEAT, true, true><<<N / 128, 256, smem1>>>(pH, W1, b1, pInv, pH1);

    // 5) BN stats
    stats_kernel<<<1024, 256>>>(pH1, pStats, N);

    // 6) fold BN+SN into W2eff/b2eff
    finalize_kernel<<<1, 128>>>(W2, b2, gamma, beta, pStats, pInv, pW2eff, pB2eff, N);

    // 7) out = h1 @ W2eff^T + b2eff
    int smem2 = (128 * NHID * 2 + NHID * 128 + 128) * (int)sizeof(float);
    cudaFuncSetAttribute(gemm_kernel<NHID, false, false>,
                         cudaFuncAttributeMaxDynamicSharedMemorySize, smem2);
    gemm_kernel<NHID, false, false><<<N / 128, 256, smem2>>>(pH1, pW2eff, pB2eff, nullptr,
                                                             (float*)d_out);
}

// round 4
// speedup vs baseline: 1.2086x; 1.1576x over previous
#include <cuda_runtime.h>
#include <cuda_bf16.h>
#include <cstdint>

#define NFEAT 64
#define NHID  128
#define MAXN  65536
#define MAXE  1048576

typedef unsigned long long ull;
typedef unsigned short ushort_t;

// ---------------- device scratch (allocation-free contract) ----------------
__device__ __align__(256) float g_h[MAXN * NFEAT];      // x + agg
__device__ __align__(256) float g_h1[MAXN * NHID];      // relu(SN-lin1) output
__device__ __align__(256) float g_stats[256];           // [0:128) sum, [128:256) sumsq
__device__ __align__(256) float g_inv_sigma[2];
__device__ __align__(256) float g_b2eff[NHID];
__device__ __align__(256) ushort_t g_wsplit1[NHID * NFEAT * 3];   // bf16 split W1/sigma1
__device__ __align__(256) ushort_t g_wsplit2[NHID * NHID * 3];    // bf16 split W2eff
__device__ int g_idx_mode;                              // 0 = int64 edges, 1 = int32 edges

// ---------------- bf16 split helpers ----------------
__device__ __forceinline__ void bsplit(float v, ushort_t& hi, ushort_t& lo) {
    __nv_bfloat16 h = __float2bfloat16(v);
    float r = v - __bfloat162float(h);
    __nv_bfloat16 l = __float2bfloat16(r);
    hi = __bfloat16_as_ushort(h);
    lo = __bfloat16_as_ushort(l);
}
__device__ __forceinline__ unsigned pk(ushort_t a, ushort_t b) {
    return (unsigned)a | ((unsigned)b << 16);
}

// ---------------- edge dtype probe + stats zero ----------------
__global__ void detect_kernel(const long long* __restrict__ ei64, int N,
                              float* __restrict__ stats) {
    int t = threadIdx.x;  // 64 threads
    long long v = ei64[t];
    unsigned bad = __ballot_sync(0xffffffffu, (v < 0 || v >= (long long)N));
    __shared__ unsigned sb[2];
    if ((t & 31) == 0) sb[t >> 5] = bad;
    __syncthreads();
    if (t == 0) g_idx_mode = (sb[0] | sb[1]) ? 1 : 0;
    stats[t] = 0.f; stats[t + 64] = 0.f; stats[t + 128] = 0.f; stats[t + 192] = 0.f;
}

// ---------------- spectral norm (tiny) ----------------
__device__ float block_reduce_sum256(float v, float* sred) {
    int t = threadIdx.x;
    sred[t] = v;
    __syncthreads();
    for (int s = 128; s > 0; s >>= 1) {
        if (t < s) sred[t] += sred[t + s];
        __syncthreads();
    }
    float r = sred[0];
    __syncthreads();
    return r;
}

__device__ void compute_inv_sigma(const float* __restrict__ W, const float* __restrict__ u,
                                  int n, int m, float* out, float* sv, float* sred) {
    int t = threadIdx.x;
    float vt = 0.f;
    if (t < m) {
        for (int i = 0; i < n; i++) vt += W[i * m + t] * u[i];
    }
    float s = block_reduce_sum256((t < m) ? vt * vt : 0.f, sred);
    if (t < m) sv[t] = vt / (sqrtf(s) + 1e-12f);
    __syncthreads();
    float wv = 0.f;
    if (t < n) {
        for (int k = 0; k < m; k++) wv += W[t * m + k] * sv[k];
    }
    float s2 = block_reduce_sum256((t < n) ? wv * wv : 0.f, sred);
    if (t == 0) {
        float sig = s2 / (sqrtf(s2) + 1e-12f);
        *out = 1.f / sig;
    }
    __syncthreads();
}

__global__ void prep_kernel(const float* __restrict__ W1, const float* __restrict__ u1,
                            const float* __restrict__ W2, const float* __restrict__ u2,
                            float* __restrict__ inv_sigma) {
    __shared__ float sv[128];
    __shared__ float sred[256];
    compute_inv_sigma(W1, u1, NHID, NFEAT, &inv_sigma[0], sv, sred);
    compute_inv_sigma(W2, u2, NHID, NHID, &inv_sigma[1], sv, sred);
}

// ---------------- split W1/sigma1 into bf16 triplets ----------------
__global__ void wsplit1_kernel(const float* __restrict__ W1,
                               const float* __restrict__ inv_sigma,
                               ushort_t* __restrict__ ws) {
    int i = blockIdx.x * blockDim.x + threadIdx.x;  // over 128*64
    if (i >= NHID * NFEAT) return;
    float w = W1[i] * inv_sigma[0];
    ushort_t hi, lo;
    bsplit(w, hi, lo);
    int f = i / NFEAT, k = i - f * NFEAT;
    ushort_t* p = ws + (size_t)f * (NFEAT * 3) + 3 * k;
    p[0] = hi; p[1] = hi; p[2] = lo;   // B' = (hi, hi, lo)
}

// ---------------- init: h = x ----------------
__global__ void init_kernel(const float4* __restrict__ x4, float4* __restrict__ h4, int n4) {
    int i = blockIdx.x * blockDim.x + threadIdx.x;
    if (i < n4) h4[i] = x4[i];
}

// ---------------- scatter: h[dst] += x[src], vectorized red, 8 thr/edge ----------------
__global__ void scatter_kernel(const void* __restrict__ eiv,
                               const float4* __restrict__ x4,
                               float4* __restrict__ h4, int E, int N) {
    int i = blockIdx.x * blockDim.x + threadIdx.x;
    if (i >= E * 8) return;
    int e = i >> 3;
    int c = i & 7;
    long long s, d;
    if (g_idx_mode == 0) {
        const long long* ei = (const long long*)eiv;
        s = ei[e];
        d = ei[E + e];
    } else {
        const int* ei = (const int*)eiv;
        s = ei[e];
        d = ei[E + e];
    }
    if ((ull)s >= (ull)N || (ull)d >= (ull)N) return;  // safety: never IMA
    const float4* xs = x4 + s * 16 + c;
    float4 v0 = __ldg(xs);
    float4 v1 = __ldg(xs + 8);
    float4* p = h4 + d * 16 + c;
    asm volatile("red.global.add.v4.f32 [%0], {%1,%2,%3,%4};"
                 :: "l"(p), "f"(v0.x), "f"(v0.y), "f"(v0.z), "f"(v0.w) : "memory");
    asm volatile("red.global.add.v4.f32 [%0], {%1,%2,%3,%4};"
                 :: "l"(p + 8), "f"(v1.x), "f"(v1.y), "f"(v1.z), "f"(v1.w) : "memory");
}

// ---------------- tensor-core GEMM via bf16 3-way split ----------------
// out[r][f] = act( sum_k in[r][k] * W[f][k] + bias[f] ),  W pre-split in global.
// Tile: 128 rows x 128 feats per block, 256 threads (8 warps = 2x4 warp grid),
// warp tile = 64 rows x 32 feats = 4x4 m16n8k16 mma per k-step.
// A' per k: (hi_a, lo_a, hi_a); B' per k: (hi_b, hi_b, lo_b)  =>
// dot = hi*hi + lo_a*hi_b + hi_a*lo_b  (drops lo*lo ~ 2^-18).
template <int K_ORIG, bool RELU>
__global__ void __launch_bounds__(256) gemm_bf16_kernel(
    const float* __restrict__ in, const ushort_t* __restrict__ wsplit,
    const float* __restrict__ bias, float* __restrict__ out) {
    constexpr int KB = 3 * K_ORIG;        // split-K length
    constexpr int KSTEPS = KB / 16;
    constexpr int SA = KB + 8;            // padded row stride (elems)
    constexpr int K4 = K_ORIG / 4;

    extern __shared__ ushort_t smu[];
    ushort_t* sA = smu;                   // 128 * SA
    ushort_t* sB = smu + 128 * SA;        // 128 * SA
    float* sBias = reinterpret_cast<float*>(smu + 2 * 128 * SA);  // 128 floats

    const int tid = threadIdx.x;
    const int row0 = blockIdx.x * 128;

    // ---- fill B (copy pre-split weights, uint4 = 8 bf16) ----
    {
        const uint4* wg = reinterpret_cast<const uint4*>(wsplit);
        constexpr int ROW4 = KB / 8;
        for (int q = tid; q < 128 * ROW4; q += 256) {
            int f = q / ROW4, c = q - f * ROW4;
            *reinterpret_cast<uint4*>(&sB[f * SA + c * 8]) = wg[q];
        }
        if (tid < 128) sBias[tid] = bias[tid];
    }

    // ---- fill A (split fp32 -> bf16 triplets) ----
    {
        const float4* in4 = reinterpret_cast<const float4*>(in) + (size_t)row0 * K4;
        for (int q = tid; q < 128 * K4; q += 256) {
            int r = q / K4, c = q - r * K4;
            float4 v = in4[(size_t)r * K4 + c];
            ushort_t h0, l0, h1, l1, h2, l2, h3, l3;
            bsplit(v.x, h0, l0); bsplit(v.y, h1, l1);
            bsplit(v.z, h2, l2); bsplit(v.w, h3, l3);
            unsigned* d32 = reinterpret_cast<unsigned*>(&sA[r * SA + c * 12]);
            d32[0] = pk(h0, l0); d32[1] = pk(h0, h1); d32[2] = pk(l1, h1);
            d32[3] = pk(h2, l2); d32[4] = pk(h2, h3); d32[5] = pk(l3, h3);
        }
    }
    __syncthreads();

    const int wid = tid >> 5;
    const int lane = tid & 31;
    const int g = lane >> 2;      // 0..7
    const int tg = lane & 3;      // 0..3
    const int rowBase = (wid >> 2) * 64;   // 0 or 64
    const int colBase = (wid & 3) * 32;    // 0,32,64,96

    float acc[4][4][4];
#pragma unroll
    for (int m = 0; m < 4; m++)
#pragma unroll
        for (int n = 0; n < 4; n++)
#pragma unroll
            for (int i = 0; i < 4; i++) acc[m][n][i] = 0.f;

    const ushort_t* aw = sA + (rowBase + g) * SA + tg * 2;
    const ushort_t* bw = sB + (colBase + g) * SA + tg * 2;

#pragma unroll
    for (int kk = 0; kk < KSTEPS; kk++) {
        const int ko = kk * 16;
        unsigned a[4][4];
#pragma unroll
        for (int m = 0; m < 4; m++) {
            const ushort_t* p = aw + m * 16 * SA + ko;
            a[m][0] = *reinterpret_cast<const unsigned*>(p);
            a[m][1] = *reinterpret_cast<const unsigned*>(p + 8 * SA);
            a[m][2] = *reinterpret_cast<const unsigned*>(p + 8);
            a[m][3] = *reinterpret_cast<const unsigned*>(p + 8 * SA + 8);
        }
        unsigned b[4][2];
#pragma unroll
        for (int n = 0; n < 4; n++) {
            const ushort_t* p = bw + n * 8 * SA + ko;
            b[n][0] = *reinterpret_cast<const unsigned*>(p);
            b[n][1] = *reinterpret_cast<const unsigned*>(p + 8);
        }
#pragma unroll
        for (int m = 0; m < 4; m++)
#pragma unroll
            for (int n = 0; n < 4; n++) {
                asm volatile(
                    "mma.sync.aligned.m16n8k16.row.col.f32.bf16.bf16.f32 "
                    "{%0,%1,%2,%3}, {%4,%5,%6,%7}, {%8,%9}, {%0,%1,%2,%3};"
                    : "+f"(acc[m][n][0]), "+f"(acc[m][n][1]),
                      "+f"(acc[m][n][2]), "+f"(acc[m][n][3])
                    : "r"(a[m][0]), "r"(a[m][1]), "r"(a[m][2]), "r"(a[m][3]),
                      "r"(b[n][0]), "r"(b[n][1]));
            }
    }

    // ---- epilogue: bias (+relu) + store ----
#pragma unroll
    for (int m = 0; m < 4; m++) {
        int r = row0 + rowBase + m * 16 + g;
#pragma unroll
        for (int n = 0; n < 4; n++) {
            int f = colBase + n * 8 + tg * 2;
            float bx = sBias[f], by = sBias[f + 1];
            float2 o0 = make_float2(acc[m][n][0] + bx, acc[m][n][1] + by);
            float2 o1 = make_float2(acc[m][n][2] + bx, acc[m][n][3] + by);
            if (RELU) {
                o0.x = fmaxf(o0.x, 0.f); o0.y = fmaxf(o0.y, 0.f);
                o1.x = fmaxf(o1.x, 0.f); o1.y = fmaxf(o1.y, 0.f);
            }
            *reinterpret_cast<float2*>(&out[(size_t)r * 128 + f]) = o0;
            *reinterpret_cast<float2*>(&out[(size_t)(r + 8) * 128 + f]) = o1;
        }
    }
}

// ---------------- column stats of h1 (post-relu) ----------------
__global__ void stats_kernel(const float* __restrict__ h1, float* __restrict__ stats, int N) {
    int f = threadIdx.x & 127;
    int sub = threadIdx.x >> 7;
    float s = 0.f, ss = 0.f;
    for (int row = blockIdx.x * 2 + sub; row < N; row += gridDim.x * 2) {
        float v = h1[(size_t)row * 128 + f];
        s += v;
        ss += v * v;
    }
    __shared__ float sh[256];
    sh[threadIdx.x] = s;
    __syncthreads();
    float stot = 0.f;
    if (sub == 0) stot = s + sh[128 + f];
    __syncthreads();
    sh[threadIdx.x] = ss;
    __syncthreads();
    if (sub == 0) {
        float sstot = ss + sh[128 + f];
        atomicAdd(&stats[f], stot);
        atomicAdd(&stats[128 + f], sstot);
    }
}

// ---------------- fold BN + SN into split W2eff / b2eff ----------------
__global__ void finalize_kernel(const float* __restrict__ W2, const float* __restrict__ b2,
                                const float* __restrict__ gamma, const float* __restrict__ beta,
                                const float* __restrict__ stats, const float* __restrict__ inv_sigma,
                                ushort_t* __restrict__ ws2, float* __restrict__ b2eff, int N) {
    __shared__ float a[128], c[128];
    int t = threadIdx.x;
    float invN = 1.f / (float)N;
    float mean = stats[t] * invN;
    float var = stats[128 + t] * invN - mean * mean;
    float af = gamma[t] * rsqrtf(var + 1e-5f);
    a[t] = af;
    c[t] = beta[t] - mean * af;
    __syncthreads();
    float is2 = inv_sigma[1];
    float bacc = 0.f;
    ushort_t* wrow = ws2 + (size_t)t * (NHID * 3);
    for (int f = 0; f < 128; f++) {
        float wsn = W2[t * 128 + f] * is2;
        float weff = wsn * a[f];
        ushort_t hi, lo;
        bsplit(weff, hi, lo);
        wrow[3 * f] = hi; wrow[3 * f + 1] = hi; wrow[3 * f + 2] = lo;
        bacc += c[f] * wsn;
    }
    b2eff[t] = b2[t] + bacc;
}

// ---------------- launch ----------------
extern "C" void kernel_launch(void* const* d_in, const int* in_sizes, int n_in,
                              void* d_out, int out_size) {
    const float* x        = (const float*)d_in[0];
    const void*  ei       = d_in[1];
    const float* W1       = (const float*)d_in[2];
    const float* b1       = (const float*)d_in[3];
    const float* u1       = (const float*)d_in[4];
    const float* gamma    = (const float*)d_in[5];
    const float* beta     = (const float*)d_in[6];
    const float* W2       = (const float*)d_in[7];
    const float* b2       = (const float*)d_in[8];
    const float* u2       = (const float*)d_in[9];

    int N = in_sizes[0] / NFEAT;
    int E = in_sizes[1] / 2;

    float *pH, *pH1, *pStats, *pInv, *pB2eff;
    ushort_t *pWs1, *pWs2;
    cudaGetSymbolAddress((void**)&pH, g_h);
    cudaGetSymbolAddress((void**)&pH1, g_h1);
    cudaGetSymbolAddress((void**)&pStats, g_stats);
    cudaGetSymbolAddress((void**)&pInv, g_inv_sigma);
    cudaGetSymbolAddress((void**)&pB2eff, g_b2eff);
    cudaGetSymbolAddress((void**)&pWs1, g_wsplit1);
    cudaGetSymbolAddress((void**)&pWs2, g_wsplit2);

    // 0) probe edge index dtype (int64 vs int32) + zero stats
    detect_kernel<<<1, 64>>>((const long long*)ei, N, pStats);

    // 1) spectral norms
    prep_kernel<<<1, 256>>>(W1, u1, W2, u2, pInv);

    // 2) split W1/sigma1 -> bf16 triplets
    wsplit1_kernel<<<(NHID * NFEAT + 255) / 256, 256>>>(W1, pInv, pWs1);

    // 3) h = x
    int n4 = N * NFEAT / 4;
    init_kernel<<<(n4 + 255) / 256, 256>>>((const float4*)x, (float4*)pH, n4);

    // 4) scatter-add h[dst] += x[src]
    int items = E * 8;
    scatter_kernel<<<(items + 255) / 256, 256>>>(ei, (const float4*)x, (float4*)pH, E, N);

    // 5) h1 = relu(h @ (W1/sigma1)^T + b1)   [tensor core]
    {
        constexpr int SA = 3 * NFEAT + 8;
        int smem = (2 * 128 * SA) * 2 + 128 * 4;
        cudaFuncSetAttribute(gemm_bf16_kernel<NFEAT, true>,
                             cudaFuncAttributeMaxDynamicSharedMemorySize, smem);
        gemm_bf16_kernel<NFEAT, true><<<N / 128, 256, smem>>>(pH, pWs1, b1, pH1);
    }

    // 6) BN stats
    stats_kernel<<<1024, 256>>>(pH1, pStats, N);

    // 7) fold BN+SN into split W2eff / b2eff
    finalize_kernel<<<1, 128>>>(W2, b2, gamma, beta, pStats, pInv, pWs2, pB2eff, N);

    // 8) out = h1 @ W2eff^T + b2eff   [tensor core]
    {
        constexpr int SA = 3 * NHID + 8;
        int smem = (2 * 128 * SA) * 2 + 128 * 4;
        cudaFuncSetAttribute(gemm_bf16_kernel<NHID, false>,
                             cudaFuncAttributeMaxDynamicSharedMemorySize, smem);
        gemm_bf16_kernel<NHID, false><<<N / 128, 256, smem>>>(pH1, pWs2, pB2eff, (float*)d_out);
    }
}

// round 5
// speedup vs baseline: 1.4996x; 1.2408x over previous
#include <cuda_runtime.h>
#include <cuda_bf16.h>
#include <cstdint>

#define NFEAT 64
#define NHID  128
#define MAXN  65536

typedef unsigned long long ull;
typedef unsigned short ushort_t;

// ---------------- device scratch (allocation-free contract) ----------------
__device__ __align__(256) float g_h[MAXN * NFEAT];      // x + agg
__device__ __align__(256) float g_h1[MAXN * NHID];      // relu(SN-lin1) output
__device__ __align__(256) float g_stats[256];           // [0:128) sum, [128:256) sumsq
__device__ __align__(256) float g_inv_sigma[2];
__device__ __align__(256) float g_b2eff[NHID];
__device__ __align__(256) ushort_t g_w1hi[NHID * NFEAT];
__device__ __align__(256) ushort_t g_w1lo[NHID * NFEAT];
__device__ __align__(256) ushort_t g_w2hi[NHID * NHID];
__device__ __align__(256) ushort_t g_w2lo[NHID * NHID];
__device__ int g_idx_mode;                              // 0 = int64 edges, 1 = int32 edges

// ---------------- bf16 split helpers ----------------
__device__ __forceinline__ void bsplit(float v, ushort_t& hi, ushort_t& lo) {
    __nv_bfloat16 h = __float2bfloat16(v);
    float r = v - __bfloat162float(h);
    __nv_bfloat16 l = __float2bfloat16(r);
    hi = __bfloat16_as_ushort(h);
    lo = __bfloat16_as_ushort(l);
}
__device__ __forceinline__ unsigned pk(ushort_t a, ushort_t b) {
    return (unsigned)a | ((unsigned)b << 16);
}

// ---------------- setup: detect + stats zero + spectral norms + W1 split ----------------
__device__ float block_reduce_sum256(float v, float* sred) {
    int t = threadIdx.x;
    sred[t] = v;
    __syncthreads();
    for (int s = 128; s > 0; s >>= 1) {
        if (t < s) sred[t] += sred[t + s];
        __syncthreads();
    }
    float r = sred[0];
    __syncthreads();
    return r;
}

__device__ float inv_sigma_calc(const float* __restrict__ W, const float* __restrict__ u,
                                int n, int m, float* sv, float* sred) {
    int t = threadIdx.x;
    float vt = 0.f;
    if (t < m) {
        for (int i = 0; i < n; i++) vt += W[i * m + t] * u[i];
    }
    float s = block_reduce_sum256((t < m) ? vt * vt : 0.f, sred);
    if (t < m) sv[t] = vt / (sqrtf(s) + 1e-12f);
    __syncthreads();
    float wv = 0.f;
    if (t < n) {
        for (int k = 0; k < m; k++) wv += W[t * m + k] * sv[k];
    }
    float s2 = block_reduce_sum256((t < n) ? wv * wv : 0.f, sred);
    float sig = s2 / (sqrtf(s2) + 1e-12f);
    return 1.f / sig;
}

__global__ void setup_kernel(const long long* __restrict__ ei64, int N,
                             float* __restrict__ stats,
                             const float* __restrict__ W1, const float* __restrict__ u1,
                             const float* __restrict__ W2, const float* __restrict__ u2,
                             float* __restrict__ inv_sigma,
                             ushort_t* __restrict__ w1hi, ushort_t* __restrict__ w1lo) {
    __shared__ float sv[128];
    __shared__ float sred[256];
    __shared__ int sbad;
    int t = threadIdx.x;
    stats[t] = 0.f;
    if (t == 0) sbad = 0;
    __syncthreads();
    if (t < 64) {
        long long v = ei64[t];
        if (v < 0 || v >= (long long)N) atomicExch(&sbad, 1);
    }
    __syncthreads();
    if (t == 0) g_idx_mode = sbad;

    float is1 = inv_sigma_calc(W1, u1, NHID, NFEAT, sv, sred);
    float is2 = inv_sigma_calc(W2, u2, NHID, NHID, sv, sred);
    if (t == 0) { inv_sigma[0] = is1; inv_sigma[1] = is2; }

    // split W1 * is1 -> bf16 hi/lo
    for (int i = t; i < NHID * NFEAT; i += 256) {
        float w = W1[i] * is1;
        ushort_t hi, lo;
        bsplit(w, hi, lo);
        w1hi[i] = hi;
        w1lo[i] = lo;
    }
}

// ---------------- scatter: h[dst] += x[src], vectorized red, 8 thr/edge ----------------
__global__ void scatter_kernel(const void* __restrict__ eiv,
                               const float4* __restrict__ x4,
                               float4* __restrict__ h4, int E, int N) {
    int i = blockIdx.x * blockDim.x + threadIdx.x;
    if (i >= E * 8) return;
    int e = i >> 3;
    int c = i & 7;
    long long s, d;
    if (g_idx_mode == 0) {
        const long long* ei = (const long long*)eiv;
        s = ei[e];
        d = ei[E + e];
    } else {
        const int* ei = (const int*)eiv;
        s = ei[e];
        d = ei[E + e];
    }
    if ((ull)s >= (ull)N || (ull)d >= (ull)N) return;  // safety: never IMA
    const float4* xs = x4 + s * 16 + c;
    float4 v0 = __ldg(xs);
    float4 v1 = __ldg(xs + 8);
    float4* p = h4 + d * 16 + c;
    asm volatile("red.global.add.v4.f32 [%0], {%1,%2,%3,%4};"
                 :: "l"(p), "f"(v0.x), "f"(v0.y), "f"(v0.z), "f"(v0.w) : "memory");
    asm volatile("red.global.add.v4.f32 [%0], {%1,%2,%3,%4};"
                 :: "l"(p + 8), "f"(v1.x), "f"(v1.y), "f"(v1.z), "f"(v1.w) : "memory");
}

// ---------------- tensor-core GEMM, compact hi/lo segments ----------------
// out[r][f] = act( sum_k in[r][k]*W[f][k] + bias[f] )
// fp32 = bf16 3-term: hi*hi + lo*hi + hi*lo  (drops lo*lo ~2^-18).
// 128x128 tile, 512 threads = 4x4 warps, warp tile 32 rows x 32 cols.
template <int K, bool RELU, bool STATS, int MINCTA>
__global__ void __launch_bounds__(512, MINCTA) gemm_kernel(
    const float* __restrict__ in,
    const ushort_t* __restrict__ whi, const ushort_t* __restrict__ wlo,
    const float* __restrict__ bias, float* __restrict__ out,
    float* __restrict__ gstats) {
    constexpr int SAe = K + 8;
    constexpr int K4 = K / 4;
    constexpr int R8 = K / 8;
    extern __shared__ ushort_t smu[];
    ushort_t* sAhi = smu;
    ushort_t* sAlo = smu + 128 * SAe;
    ushort_t* sBhi = smu + 2 * 128 * SAe;
    ushort_t* sBlo = smu + 3 * 128 * SAe;
    float* sBias   = reinterpret_cast<float*>(smu + 4 * 128 * SAe);
    float* sStats  = sBias + 128;

    const int tid = threadIdx.x;
    const int row0 = blockIdx.x * 128;

    // B fill: copy pre-split weights (uint4 = 8 bf16)
    {
        const uint4* ghi = reinterpret_cast<const uint4*>(whi);
        const uint4* glo = reinterpret_cast<const uint4*>(wlo);
        for (int q = tid; q < 128 * R8; q += 512) {
            int f = q / R8, c = q - f * R8;
            *reinterpret_cast<uint4*>(&sBhi[f * SAe + c * 8]) = ghi[q];
            *reinterpret_cast<uint4*>(&sBlo[f * SAe + c * 8]) = glo[q];
        }
    }
    // A fill: split fp32 -> bf16 hi/lo
    {
        const float4* in4 = reinterpret_cast<const float4*>(in);
        for (int q = tid; q < 128 * K4; q += 512) {
            int r = q / K4, c = q - r * K4;
            float4 v = in4[(size_t)(row0 + r) * K4 + c];
            ushort_t h0, l0, h1, l1, h2, l2, h3, l3;
            bsplit(v.x, h0, l0); bsplit(v.y, h1, l1);
            bsplit(v.z, h2, l2); bsplit(v.w, h3, l3);
            uint2 hw, lw;
            hw.x = pk(h0, h1); hw.y = pk(h2, h3);
            lw.x = pk(l0, l1); lw.y = pk(l2, l3);
            *reinterpret_cast<uint2*>(&sAhi[r * SAe + c * 4]) = hw;
            *reinterpret_cast<uint2*>(&sAlo[r * SAe + c * 4]) = lw;
        }
    }
    if (tid < 128) sBias[tid] = bias[tid];
    if (STATS && tid < 256) sStats[tid] = 0.f;
    __syncthreads();

    const int wid = tid >> 5;
    const int lane = tid & 31;
    const int g = lane >> 2;
    const int tg = lane & 3;
    const int rowBase = (wid >> 2) * 32;
    const int colBase = (wid & 3) * 32;

    float acc[2][4][4];
#pragma unroll
    for (int m = 0; m < 2; m++)
#pragma unroll
        for (int n = 0; n < 4; n++)
#pragma unroll
            for (int i = 0; i < 4; i++) acc[m][n][i] = 0.f;

    const int aoff = (rowBase + g) * SAe + tg * 2;
    const int boff = (colBase + g) * SAe + tg * 2;

#define MMA(ACC, A, B)                                                         \
    asm volatile(                                                              \
        "mma.sync.aligned.m16n8k16.row.col.f32.bf16.bf16.f32 "                 \
        "{%0,%1,%2,%3}, {%4,%5,%6,%7}, {%8,%9}, {%0,%1,%2,%3};"                \
        : "+f"((ACC)[0]), "+f"((ACC)[1]), "+f"((ACC)[2]), "+f"((ACC)[3])       \
        : "r"((A)[0]), "r"((A)[1]), "r"((A)[2]), "r"((A)[3]),                  \
          "r"((B)[0]), "r"((B)[1]))

#pragma unroll
    for (int kk = 0; kk < K / 16; kk++) {
        const int ko = kk * 16;
        unsigned ahi[2][4], bhi[4][2];
#pragma unroll
        for (int m = 0; m < 2; m++) {
            int base = aoff + m * 16 * SAe + ko;
            ahi[m][0] = *reinterpret_cast<const unsigned*>(&sAhi[base]);
            ahi[m][1] = *reinterpret_cast<const unsigned*>(&sAhi[base + 8 * SAe]);
            ahi[m][2] = *reinterpret_cast<const unsigned*>(&sAhi[base + 8]);
            ahi[m][3] = *reinterpret_cast<const unsigned*>(&sAhi[base + 8 * SAe + 8]);
        }
#pragma unroll
        for (int n = 0; n < 4; n++) {
            int base = boff + n * 8 * SAe + ko;
            bhi[n][0] = *reinterpret_cast<const unsigned*>(&sBhi[base]);
            bhi[n][1] = *reinterpret_cast<const unsigned*>(&sBhi[base + 8]);
        }
#pragma unroll
        for (int m = 0; m < 2; m++)
#pragma unroll
            for (int n = 0; n < 4; n++) MMA(acc[m][n], ahi[m], bhi[n]);

        // seg3: ahi x blo (reuse bhi regs)
        unsigned blo[4][2];
#pragma unroll
        for (int n = 0; n < 4; n++) {
            int base = boff + n * 8 * SAe + ko;
            blo[n][0] = *reinterpret_cast<const unsigned*>(&sBlo[base]);
            blo[n][1] = *reinterpret_cast<const unsigned*>(&sBlo[base + 8]);
        }
#pragma unroll
        for (int m = 0; m < 2; m++)
#pragma unroll
            for (int n = 0; n < 4; n++) MMA(acc[m][n], ahi[m], blo[n]);

        // seg2: alo x bhi
        unsigned alo[2][4];
#pragma unroll
        for (int m = 0; m < 2; m++) {
            int base = aoff + m * 16 * SAe + ko;
            alo[m][0] = *reinterpret_cast<const unsigned*>(&sAlo[base]);
            alo[m][1] = *reinterpret_cast<const unsigned*>(&sAlo[base + 8 * SAe]);
            alo[m][2] = *reinterpret_cast<const unsigned*>(&sAlo[base + 8]);
            alo[m][3] = *reinterpret_cast<const unsigned*>(&sAlo[base + 8 * SAe + 8]);
        }
#pragma unroll
        for (int n = 0; n < 4; n++) {
            int base = boff + n * 8 * SAe + ko;
            bhi[n][0] = *reinterpret_cast<const unsigned*>(&sBhi[base]);
            bhi[n][1] = *reinterpret_cast<const unsigned*>(&sBhi[base + 8]);
        }
#pragma unroll
        for (int m = 0; m < 2; m++)
#pragma unroll
            for (int n = 0; n < 4; n++) MMA(acc[m][n], alo[m], bhi[n]);
    }
#undef MMA

    // ---- epilogue ----
    float cs[4][2], css[4][2];
    if (STATS) {
#pragma unroll
        for (int n = 0; n < 4; n++) { cs[n][0] = cs[n][1] = css[n][0] = css[n][1] = 0.f; }
    }
#pragma unroll
    for (int m = 0; m < 2; m++) {
        int r = row0 + rowBase + m * 16 + g;
#pragma unroll
        for (int n = 0; n < 4; n++) {
            int f = colBase + n * 8 + tg * 2;
            float bx = sBias[f], by = sBias[f + 1];
            float2 o0 = make_float2(acc[m][n][0] + bx, acc[m][n][1] + by);
            float2 o1 = make_float2(acc[m][n][2] + bx, acc[m][n][3] + by);
            if (RELU) {
                o0.x = fmaxf(o0.x, 0.f); o0.y = fmaxf(o0.y, 0.f);
                o1.x = fmaxf(o1.x, 0.f); o1.y = fmaxf(o1.y, 0.f);
            }
            if (STATS) {
                cs[n][0] += o0.x + o1.x;  cs[n][1] += o0.y + o1.y;
                css[n][0] += o0.x * o0.x + o1.x * o1.x;
                css[n][1] += o0.y * o0.y + o1.y * o1.y;
            }
            *reinterpret_cast<float2*>(&out[(size_t)r * 128 + f]) = o0;
            *reinterpret_cast<float2*>(&out[(size_t)(r + 8) * 128 + f]) = o1;
        }
    }
    if (STATS) {
#pragma unroll
        for (int mask = 4; mask < 32; mask <<= 1) {
#pragma unroll
            for (int n = 0; n < 4; n++) {
#pragma unroll
                for (int j = 0; j < 2; j++) {
                    cs[n][j] += __shfl_xor_sync(0xffffffffu, cs[n][j], mask);
                    css[n][j] += __shfl_xor_sync(0xffffffffu, css[n][j], mask);
                }
            }
        }
        if (lane < 4) {  // g == 0, tg == lane
#pragma unroll
            for (int n = 0; n < 4; n++) {
#pragma unroll
                for (int j = 0; j < 2; j++) {
                    int f = colBase + n * 8 + lane * 2 + j;
                    atomicAdd(&sStats[f], cs[n][j]);
                    atomicAdd(&sStats[128 + f], css[n][j]);
                }
            }
        }
        __syncthreads();
        if (tid < 256) atomicAdd(&gstats[tid], sStats[tid]);
    }
}

// ---------------- fold BN + SN into split W2eff / b2eff ----------------
__global__ void finalize_kernel(const float* __restrict__ W2, const float* __restrict__ b2,
                                const float* __restrict__ gamma, const float* __restrict__ beta,
                                const float* __restrict__ stats, const float* __restrict__ inv_sigma,
                                ushort_t* __restrict__ w2hi, ushort_t* __restrict__ w2lo,
                                float* __restrict__ b2eff, int N) {
    __shared__ float a[128], c[128];
    int t = threadIdx.x;
    float invN = 1.f / (float)N;
    float mean = stats[t] * invN;
    float var = stats[128 + t] * invN - mean * mean;
    float af = gamma[t] * rsqrtf(var + 1e-5f);
    a[t] = af;
    c[t] = beta[t] - mean * af;
    __syncthreads();
    float is2 = inv_sigma[1];
    float bacc = 0.f;
    ushort_t* rhi = w2hi + (size_t)t * NHID;
    ushort_t* rlo = w2lo + (size_t)t * NHID;
    for (int f = 0; f < 128; f++) {
        float wsn = W2[t * 128 + f] * is2;
        float weff = wsn * a[f];
        ushort_t hi, lo;
        bsplit(weff, hi, lo);
        rhi[f] = hi;
        rlo[f] = lo;
        bacc += c[f] * wsn;
    }
    b2eff[t] = b2[t] + bacc;
}

// ---------------- launch ----------------
extern "C" void kernel_launch(void* const* d_in, const int* in_sizes, int n_in,
                              void* d_out, int out_size) {
    const float* x        = (const float*)d_in[0];
    const void*  ei       = d_in[1];
    const float* W1       = (const float*)d_in[2];
    const float* b1       = (const float*)d_in[3];
    const float* u1       = (const float*)d_in[4];
    const float* gamma    = (const float*)d_in[5];
    const float* beta     = (const float*)d_in[6];
    const float* W2       = (const float*)d_in[7];
    const float* b2       = (const float*)d_in[8];
    const float* u2       = (const float*)d_in[9];

    int N = in_sizes[0] / NFEAT;
    int E = in_sizes[1] / 2;

    float *pH, *pH1, *pStats, *pInv, *pB2eff;
    ushort_t *pW1hi, *pW1lo, *pW2hi, *pW2lo;
    cudaGetSymbolAddress((void**)&pH, g_h);
    cudaGetSymbolAddress((void**)&pH1, g_h1);
    cudaGetSymbolAddress((void**)&pStats, g_stats);
    cudaGetSymbolAddress((void**)&pInv, g_inv_sigma);
    cudaGetSymbolAddress((void**)&pB2eff, g_b2eff);
    cudaGetSymbolAddress((void**)&pW1hi, g_w1hi);
    cudaGetSymbolAddress((void**)&pW1lo, g_w1lo);
    cudaGetSymbolAddress((void**)&pW2hi, g_w2hi);
    cudaGetSymbolAddress((void**)&pW2lo, g_w2lo);

    // 1) setup: edge dtype probe + stats zero + spectral norms + W1 split
    setup_kernel<<<1, 256>>>((const long long*)ei, N, pStats, W1, u1, W2, u2,
                             pInv, pW1hi, pW1lo);

    // 2) h = x  (async D2D copy, graph-capturable)
    cudaMemcpyAsync(pH, x, (size_t)N * NFEAT * sizeof(float), cudaMemcpyDeviceToDevice);

    // 3) scatter-add h[dst] += x[src]
    int items = E * 8;
    scatter_kernel<<<(items + 255) / 256, 256>>>(ei, (const float4*)x, (float4*)pH, E, N);

    // 4) h1 = relu(h @ (W1/s1)^T + b1), fused BN-stats
    {
        constexpr int SAe = NFEAT + 8;
        int smem = 4 * 128 * SAe * 2 + 128 * 4 + 256 * 4;
        cudaFuncSetAttribute((const void*)gemm_kernel<NFEAT, true, true, 2>,
                             cudaFuncAttributeMaxDynamicSharedMemorySize, smem);
        gemm_kernel<NFEAT, true, true, 2><<<N / 128, 512, smem>>>(
            pH, pW1hi, pW1lo, b1, pH1, pStats);
    }

    // 5) fold BN+SN into split W2eff / b2eff
    finalize_kernel<<<1, 128>>>(W2, b2, gamma, beta, pStats, pInv, pW2hi, pW2lo, pB2eff, N);

    // 6) out = h1 @ W2eff^T + b2eff
    {
        constexpr int SAe = NHID + 8;
        int smem = 4 * 128 * SAe * 2 + 128 * 4 + 256 * 4;
        cudaFuncSetAttribute((const void*)gemm_kernel<NHID, false, false, 1>,
                             cudaFuncAttributeMaxDynamicSharedMemorySize, smem);
        gemm_kernel<NHID, false, false, 1><<<N / 128, 512, smem>>>(
            pH1, pW2hi, pW2lo, pB2eff, (float*)d_out, nullptr);
    }
}

// round 6
// speedup vs baseline: 1.9670x; 1.3117x over previous
#include <cuda_runtime.h>
#include <cuda_bf16.h>
#include <cstdint>

#define NFEAT 64
#define NHID  128
#define MAXN  65536

typedef unsigned long long ull;
typedef unsigned short ushort_t;

// ---------------- device scratch (allocation-free contract) ----------------
__device__ __align__(256) float g_h[MAXN * NFEAT];      // x + agg
__device__ __align__(256) float g_h1[MAXN * NHID];      // relu(SN-lin1) output
__device__ __align__(256) float g_stats[256];           // [0:128) sum, [128:256) sumsq
__device__ __align__(256) float g_inv_sigma[2];
__device__ __align__(256) float g_b2eff[NHID];
__device__ __align__(256) ushort_t g_w1hi[NHID * NFEAT];
__device__ __align__(256) ushort_t g_w1lo[NHID * NFEAT];
__device__ __align__(256) ushort_t g_w2hi[NHID * NHID];
__device__ __align__(256) ushort_t g_w2lo[NHID * NHID];
__device__ int g_idx_mode;                              // 0 = int64 edges, 1 = int32 edges

// ---------------- bf16 split helpers ----------------
__device__ __forceinline__ void bsplit(float v, ushort_t& hi, ushort_t& lo) {
    __nv_bfloat16 h = __float2bfloat16(v);
    float r = v - __bfloat162float(h);
    __nv_bfloat16 l = __float2bfloat16(r);
    hi = __bfloat16_as_ushort(h);
    lo = __bfloat16_as_ushort(l);
}
__device__ __forceinline__ unsigned pk(ushort_t a, ushort_t b) {
    return (unsigned)a | ((unsigned)b << 16);
}

// ---------------- setup: detect + stats zero + spectral norms ----------------
__device__ float block_reduce_sum256(float v, float* sred) {
    int t = threadIdx.x;
    sred[t] = v;
    __syncthreads();
    for (int s = 128; s > 0; s >>= 1) {
        if (t < s) sred[t] += sred[t + s];
        __syncthreads();
    }
    float r = sred[0];
    __syncthreads();
    return r;
}

__device__ float inv_sigma_calc(const float* __restrict__ W, const float* __restrict__ u,
                                int n, int m, float* sv, float* sred) {
    int t = threadIdx.x;
    float vt = 0.f;
    if (t < m) {
        for (int i = 0; i < n; i++) vt += W[i * m + t] * u[i];
    }
    float s = block_reduce_sum256((t < m) ? vt * vt : 0.f, sred);
    if (t < m) sv[t] = vt / (sqrtf(s) + 1e-12f);
    __syncthreads();
    float wv = 0.f;
    if (t < n) {
        for (int k = 0; k < m; k++) wv += W[t * m + k] * sv[k];
    }
    float s2 = block_reduce_sum256((t < n) ? wv * wv : 0.f, sred);
    float sig = s2 / (sqrtf(s2) + 1e-12f);
    return 1.f / sig;
}

__global__ void setup_kernel(const long long* __restrict__ ei64, int N,
                             float* __restrict__ stats,
                             const float* __restrict__ W1, const float* __restrict__ u1,
                             const float* __restrict__ W2, const float* __restrict__ u2,
                             float* __restrict__ inv_sigma) {
    __shared__ float sv[128];
    __shared__ float sred[256];
    __shared__ int sbad;
    int t = threadIdx.x;
    stats[t] = 0.f;
    if (t == 0) sbad = 0;
    __syncthreads();
    if (t < 64) {
        long long v = ei64[t];
        if (v < 0 || v >= (long long)N) atomicExch(&sbad, 1);
    }
    __syncthreads();
    if (t == 0) g_idx_mode = sbad;

    float is1 = inv_sigma_calc(W1, u1, NHID, NFEAT, sv, sred);
    float is2 = inv_sigma_calc(W2, u2, NHID, NHID, sv, sred);
    if (t == 0) { inv_sigma[0] = is1; inv_sigma[1] = is2; }
}

// ---------------- parallel W1 split ----------------
__global__ void wsplit1_kernel(const float* __restrict__ W1,
                               const float* __restrict__ inv_sigma,
                               ushort_t* __restrict__ w1hi, ushort_t* __restrict__ w1lo) {
    int i = blockIdx.x * blockDim.x + threadIdx.x;
    if (i >= NHID * NFEAT) return;
    float w = W1[i] * inv_sigma[0];
    ushort_t hi, lo;
    bsplit(w, hi, lo);
    w1hi[i] = hi;
    w1lo[i] = lo;
}

// ---------------- scatter: h[dst] += x[src], vectorized red, 8 thr/edge ----------------
__global__ void scatter_kernel(const void* __restrict__ eiv,
                               const float4* __restrict__ x4,
                               float4* __restrict__ h4, int E, int N) {
    int i = blockIdx.x * blockDim.x + threadIdx.x;
    if (i >= E * 8) return;
    int e = i >> 3;
    int c = i & 7;
    long long s, d;
    if (g_idx_mode == 0) {
        const long long* ei = (const long long*)eiv;
        s = ei[e];
        d = ei[E + e];
    } else {
        const int* ei = (const int*)eiv;
        s = ei[e];
        d = ei[E + e];
    }
    if ((ull)s >= (ull)N || (ull)d >= (ull)N) return;  // safety: never IMA
    const float4* xs = x4 + s * 16 + c;
    float4 v0 = __ldg(xs);
    float4 v1 = __ldg(xs + 8);
    float4* p = h4 + d * 16 + c;
    asm volatile("red.global.add.v4.f32 [%0], {%1,%2,%3,%4};"
                 :: "l"(p), "f"(v0.x), "f"(v0.y), "f"(v0.z), "f"(v0.w) : "memory");
    asm volatile("red.global.add.v4.f32 [%0], {%1,%2,%3,%4};"
                 :: "l"(p + 8), "f"(v1.x), "f"(v1.y), "f"(v1.z), "f"(v1.w) : "memory");
}

// ---------------- tensor-core GEMM, compact hi/lo segments ----------------
// out[r][f] = act( sum_k in[r][k]*W[f][k] + bias[f] )
// fp32 = bf16 3-term: hi*hi + lo*hi + hi*lo  (drops lo*lo ~2^-18).
// 128x128 tile, 512 threads = 4x4 warps, warp tile 32 rows x 32 cols.
template <int K, bool RELU, bool STATS, int MINCTA>
__global__ void __launch_bounds__(512, MINCTA) gemm_kernel(
    const float* __restrict__ in,
    const ushort_t* __restrict__ whi, const ushort_t* __restrict__ wlo,
    const float* __restrict__ bias, float* __restrict__ out,
    float* __restrict__ gstats) {
    constexpr int SAe = K + 8;
    constexpr int K4 = K / 4;
    constexpr int R8 = K / 8;
    extern __shared__ ushort_t smu[];
    ushort_t* sAhi = smu;
    ushort_t* sAlo = smu + 128 * SAe;
    ushort_t* sBhi = smu + 2 * 128 * SAe;
    ushort_t* sBlo = smu + 3 * 128 * SAe;
    float* sBias   = reinterpret_cast<float*>(smu + 4 * 128 * SAe);
    float* sStats  = sBias + 128;

    const int tid = threadIdx.x;
    const int row0 = blockIdx.x * 128;

    // B fill: copy pre-split weights (uint4 = 8 bf16)
    {
        const uint4* ghi = reinterpret_cast<const uint4*>(whi);
        const uint4* glo = reinterpret_cast<const uint4*>(wlo);
        for (int q = tid; q < 128 * R8; q += 512) {
            int f = q / R8, c = q - f * R8;
            *reinterpret_cast<uint4*>(&sBhi[f * SAe + c * 8]) = ghi[q];
            *reinterpret_cast<uint4*>(&sBlo[f * SAe + c * 8]) = glo[q];
        }
    }
    // A fill: split fp32 -> bf16 hi/lo
    {
        const float4* in4 = reinterpret_cast<const float4*>(in);
        for (int q = tid; q < 128 * K4; q += 512) {
            int r = q / K4, c = q - r * K4;
            float4 v = in4[(size_t)(row0 + r) * K4 + c];
            ushort_t h0, l0, h1, l1, h2, l2, h3, l3;
            bsplit(v.x, h0, l0); bsplit(v.y, h1, l1);
            bsplit(v.z, h2, l2); bsplit(v.w, h3, l3);
            uint2 hw, lw;
            hw.x = pk(h0, h1); hw.y = pk(h2, h3);
            lw.x = pk(l0, l1); lw.y = pk(l2, l3);
            *reinterpret_cast<uint2*>(&sAhi[r * SAe + c * 4]) = hw;
            *reinterpret_cast<uint2*>(&sAlo[r * SAe + c * 4]) = lw;
        }
    }
    if (tid < 128) sBias[tid] = bias[tid];
    if (STATS && tid < 256) sStats[tid] = 0.f;
    __syncthreads();

    const int wid = tid >> 5;
    const int lane = tid & 31;
    const int g = lane >> 2;
    const int tg = lane & 3;
    const int rowBase = (wid >> 2) * 32;
    const int colBase = (wid & 3) * 32;

    float acc[2][4][4];
#pragma unroll
    for (int m = 0; m < 2; m++)
#pragma unroll
        for (int n = 0; n < 4; n++)
#pragma unroll
            for (int i = 0; i < 4; i++) acc[m][n][i] = 0.f;

    const int aoff = (rowBase + g) * SAe + tg * 2;
    const int boff = (colBase + g) * SAe + tg * 2;

#define MMA(ACC, A, B)                                                         \
    asm volatile(                                                              \
        "mma.sync.aligned.m16n8k16.row.col.f32.bf16.bf16.f32 "                 \
        "{%0,%1,%2,%3}, {%4,%5,%6,%7}, {%8,%9}, {%0,%1,%2,%3};"                \
        : "+f"((ACC)[0]), "+f"((ACC)[1]), "+f"((ACC)[2]), "+f"((ACC)[3])       \
        : "r"((A)[0]), "r"((A)[1]), "r"((A)[2]), "r"((A)[3]),                  \
          "r"((B)[0]), "r"((B)[1]))

#pragma unroll
    for (int kk = 0; kk < K / 16; kk++) {
        const int ko = kk * 16;
        unsigned ahi[2][4], bhi[4][2];
#pragma unroll
        for (int m = 0; m < 2; m++) {
            int base = aoff + m * 16 * SAe + ko;
            ahi[m][0] = *reinterpret_cast<const unsigned*>(&sAhi[base]);
            ahi[m][1] = *reinterpret_cast<const unsigned*>(&sAhi[base + 8 * SAe]);
            ahi[m][2] = *reinterpret_cast<const unsigned*>(&sAhi[base + 8]);
            ahi[m][3] = *reinterpret_cast<const unsigned*>(&sAhi[base + 8 * SAe + 8]);
        }
#pragma unroll
        for (int n = 0; n < 4; n++) {
            int base = boff + n * 8 * SAe + ko;
            bhi[n][0] = *reinterpret_cast<const unsigned*>(&sBhi[base]);
            bhi[n][1] = *reinterpret_cast<const unsigned*>(&sBhi[base + 8]);
        }
#pragma unroll
        for (int m = 0; m < 2; m++)
#pragma unroll
            for (int n = 0; n < 4; n++) MMA(acc[m][n], ahi[m], bhi[n]);

        unsigned blo[4][2];
#pragma unroll
        for (int n = 0; n < 4; n++) {
            int base = boff + n * 8 * SAe + ko;
            blo[n][0] = *reinterpret_cast<const unsigned*>(&sBlo[base]);
            blo[n][1] = *reinterpret_cast<const unsigned*>(&sBlo[base + 8]);
        }
#pragma unroll
        for (int m = 0; m < 2; m++)
#pragma unroll
            for (int n = 0; n < 4; n++) MMA(acc[m][n], ahi[m], blo[n]);

        unsigned alo[2][4];
#pragma unroll
        for (int m = 0; m < 2; m++) {
            int base = aoff + m * 16 * SAe + ko;
            alo[m][0] = *reinterpret_cast<const unsigned*>(&sAlo[base]);
            alo[m][1] = *reinterpret_cast<const unsigned*>(&sAlo[base + 8 * SAe]);
            alo[m][2] = *reinterpret_cast<const unsigned*>(&sAlo[base + 8]);
            alo[m][3] = *reinterpret_cast<const unsigned*>(&sAlo[base + 8 * SAe + 8]);
        }
#pragma unroll
        for (int n = 0; n < 4; n++) {
            int base = boff + n * 8 * SAe + ko;
            bhi[n][0] = *reinterpret_cast<const unsigned*>(&sBhi[base]);
            bhi[n][1] = *reinterpret_cast<const unsigned*>(&sBhi[base + 8]);
        }
#pragma unroll
        for (int m = 0; m < 2; m++)
#pragma unroll
            for (int n = 0; n < 4; n++) MMA(acc[m][n], alo[m], bhi[n]);
    }
#undef MMA

    // ---- epilogue ----
    float cs[4][2], css[4][2];
    if (STATS) {
#pragma unroll
        for (int n = 0; n < 4; n++) { cs[n][0] = cs[n][1] = css[n][0] = css[n][1] = 0.f; }
    }
#pragma unroll
    for (int m = 0; m < 2; m++) {
        int r = row0 + rowBase + m * 16 + g;
#pragma unroll
        for (int n = 0; n < 4; n++) {
            int f = colBase + n * 8 + tg * 2;
            float bx = sBias[f], by = sBias[f + 1];
            float2 o0 = make_float2(acc[m][n][0] + bx, acc[m][n][1] + by);
            float2 o1 = make_float2(acc[m][n][2] + bx, acc[m][n][3] + by);
            if (RELU) {
                o0.x = fmaxf(o0.x, 0.f); o0.y = fmaxf(o0.y, 0.f);
                o1.x = fmaxf(o1.x, 0.f); o1.y = fmaxf(o1.y, 0.f);
            }
            if (STATS) {
                cs[n][0] += o0.x + o1.x;  cs[n][1] += o0.y + o1.y;
                css[n][0] += o0.x * o0.x + o1.x * o1.x;
                css[n][1] += o0.y * o0.y + o1.y * o1.y;
            }
            *reinterpret_cast<float2*>(&out[(size_t)r * 128 + f]) = o0;
            *reinterpret_cast<float2*>(&out[(size_t)(r + 8) * 128 + f]) = o1;
        }
    }
    if (STATS) {
#pragma unroll
        for (int mask = 4; mask < 32; mask <<= 1) {
#pragma unroll
            for (int n = 0; n < 4; n++) {
#pragma unroll
                for (int j = 0; j < 2; j++) {
                    cs[n][j] += __shfl_xor_sync(0xffffffffu, cs[n][j], mask);
                    css[n][j] += __shfl_xor_sync(0xffffffffu, css[n][j], mask);
                }
            }
        }
        if (lane < 4) {  // g == 0, tg == lane
#pragma unroll
            for (int n = 0; n < 4; n++) {
#pragma unroll
                for (int j = 0; j < 2; j++) {
                    int f = colBase + n * 8 + lane * 2 + j;
                    atomicAdd(&sStats[f], cs[n][j]);
                    atomicAdd(&sStats[128 + f], css[n][j]);
                }
            }
        }
        __syncthreads();
        if (tid < 256) atomicAdd(&gstats[tid], sStats[tid]);
    }
}

// ---------------- parallel fold BN + SN into split W2eff / b2eff ----------------
// Block t handles W2 row t; thread f handles element (t, f). Coalesced.
__global__ void __launch_bounds__(128) finalize_kernel(
    const float* __restrict__ W2, const float* __restrict__ b2,
    const float* __restrict__ gamma, const float* __restrict__ beta,
    const float* __restrict__ stats, const float* __restrict__ inv_sigma,
    ushort_t* __restrict__ w2hi, ushort_t* __restrict__ w2lo,
    float* __restrict__ b2eff, int N) {
    const int t = blockIdx.x;   // output row
    const int f = threadIdx.x;  // input feature
    float invN = 1.f / (float)N;
    float mean = stats[f] * invN;
    float var = stats[128 + f] * invN - mean * mean;
    float af = gamma[f] * rsqrtf(var + 1e-5f);
    float cf = beta[f] - mean * af;

    float wsn = W2[t * 128 + f] * inv_sigma[1];
    float weff = wsn * af;
    ushort_t hi, lo;
    bsplit(weff, hi, lo);
    w2hi[t * 128 + f] = hi;
    w2lo[t * 128 + f] = lo;

    // bacc = sum_f cf * wsn  (block reduction)
    float v = cf * wsn;
#pragma unroll
    for (int mask = 16; mask > 0; mask >>= 1)
        v += __shfl_xor_sync(0xffffffffu, v, mask);
    __shared__ float sw[4];
    if ((f & 31) == 0) sw[f >> 5] = v;
    __syncthreads();
    if (f == 0) b2eff[t] = b2[t] + sw[0] + sw[1] + sw[2] + sw[3];
}

// ---------------- launch ----------------
extern "C" void kernel_launch(void* const* d_in, const int* in_sizes, int n_in,
                              void* d_out, int out_size) {
    const float* x        = (const float*)d_in[0];
    const void*  ei       = d_in[1];
    const float* W1       = (const float*)d_in[2];
    const float* b1       = (const float*)d_in[3];
    const float* u1       = (const float*)d_in[4];
    const float* gamma    = (const float*)d_in[5];
    const float* beta     = (const float*)d_in[6];
    const float* W2       = (const float*)d_in[7];
    const float* b2       = (const float*)d_in[8];
    const float* u2       = (const float*)d_in[9];

    int N = in_sizes[0] / NFEAT;
    int E = in_sizes[1] / 2;

    float *pH, *pH1, *pStats, *pInv, *pB2eff;
    ushort_t *pW1hi, *pW1lo, *pW2hi, *pW2lo;
    cudaGetSymbolAddress((void**)&pH, g_h);
    cudaGetSymbolAddress((void**)&pH1, g_h1);
    cudaGetSymbolAddress((void**)&pStats, g_stats);
    cudaGetSymbolAddress((void**)&pInv, g_inv_sigma);
    cudaGetSymbolAddress((void**)&pB2eff, g_b2eff);
    cudaGetSymbolAddress((void**)&pW1hi, g_w1hi);
    cudaGetSymbolAddress((void**)&pW1lo, g_w1lo);
    cudaGetSymbolAddress((void**)&pW2hi, g_w2hi);
    cudaGetSymbolAddress((void**)&pW2lo, g_w2lo);

    // 1) setup: edge dtype probe + stats zero + spectral norms
    setup_kernel<<<1, 256>>>((const long long*)ei, N, pStats, W1, u1, W2, u2, pInv);

    // 1b) parallel W1 split
    wsplit1_kernel<<<(NHID * NFEAT + 255) / 256, 256>>>(W1, pInv, pW1hi, pW1lo);

    // 2) h = x  (async D2D copy, graph-capturable)
    cudaMemcpyAsync(pH, x, (size_t)N * NFEAT * sizeof(float), cudaMemcpyDeviceToDevice);

    // 3) scatter-add h[dst] += x[src]
    int items = E * 8;
    scatter_kernel<<<(items + 255) / 256, 256>>>(ei, (const float4*)x, (float4*)pH, E, N);

    // 4) h1 = relu(h @ (W1/s1)^T + b1), fused BN-stats
    {
        constexpr int SAe = NFEAT + 8;
        int smem = 4 * 128 * SAe * 2 + 128 * 4 + 256 * 4;
        cudaFuncSetAttribute((const void*)gemm_kernel<NFEAT, true, true, 2>,
                             cudaFuncAttributeMaxDynamicSharedMemorySize, smem);
        gemm_kernel<NFEAT, true, true, 2><<<N / 128, 512, smem>>>(
            pH, pW1hi, pW1lo, b1, pH1, pStats);
    }

    // 5) parallel fold BN+SN into split W2eff / b2eff
    finalize_kernel<<<128, 128>>>(W2, b2, gamma, beta, pStats, pInv, pW2hi, pW2lo, pB2eff, N);

    // 6) out = h1 @ W2eff^T + b2eff
    {
        constexpr int SAe = NHID + 8;
        int smem = 4 * 128 * SAe * 2 + 128 * 4 + 256 * 4;
        cudaFuncSetAttribute((const void*)gemm_kernel<NHID, false, false, 1>,
                             cudaFuncAttributeMaxDynamicSharedMemorySize, smem);
        gemm_kernel<NHID, false, false, 1><<<N / 128, 512, smem>>>(
            pH1, pW2hi, pW2lo, pB2eff, (float*)d_out, nullptr);
    }
}

// round 7
// speedup vs baseline: 1.9961x; 1.0147x over previous
#include <cuda_runtime.h>
#include <cuda_bf16.h>
#include <cstdint>

#define NFEAT 64
#define NHID  128
#define MAXN  65536

typedef unsigned long long ull;
typedef unsigned short ushort_t;

// ---------------- device scratch (allocation-free contract) ----------------
__device__ __align__(256) float g_agg[MAXN * NFEAT];    // neighbor sum (zeroed)
__device__ __align__(256) float g_h1[MAXN * NHID];      // relu(SN-lin1) output
__device__ __align__(256) float g_stats[256];           // [0:128) sum, [128:256) sumsq
__device__ __align__(256) float g_inv_sigma[2];
__device__ __align__(256) float g_b2eff[NHID];
__device__ __align__(256) ushort_t g_w1hi[NHID * NFEAT];
__device__ __align__(256) ushort_t g_w1lo[NHID * NFEAT];
__device__ __align__(256) ushort_t g_w2hi[NHID * NHID];
__device__ __align__(256) ushort_t g_w2lo[NHID * NHID];
__device__ int g_idx_mode;                              // 0 = int64 edges, 1 = int32 edges

// ---------------- bf16 split helpers ----------------
__device__ __forceinline__ void bsplit(float v, ushort_t& hi, ushort_t& lo) {
    __nv_bfloat16 h = __float2bfloat16(v);
    float r = v - __bfloat162float(h);
    __nv_bfloat16 l = __float2bfloat16(r);
    hi = __bfloat16_as_ushort(h);
    lo = __bfloat16_as_ushort(l);
}
__device__ __forceinline__ unsigned pk(ushort_t a, ushort_t b) {
    return (unsigned)a | ((unsigned)b << 16);
}

// ---------------- setup: detect + stats zero + spectral norms ----------------
__device__ float block_reduce_sum256(float v, float* sred) {
    int t = threadIdx.x;
    sred[t] = v;
    __syncthreads();
    for (int s = 128; s > 0; s >>= 1) {
        if (t < s) sred[t] += sred[t + s];
        __syncthreads();
    }
    float r = sred[0];
    __syncthreads();
    return r;
}

__device__ float inv_sigma_calc(const float* __restrict__ W, const float* __restrict__ u,
                                int n, int m, float* sv, float* swv, float* sred) {
    int t = threadIdx.x;
    // v = normalize(W^T u): thread t (t < m) sums over rows, coalesced across t
    float vt = 0.f;
    if (t < m) {
#pragma unroll 4
        for (int i = 0; i < n; i++) vt += W[i * m + t] * u[i];
    }
    float s = block_reduce_sum256((t < m) ? vt * vt : 0.f, sred);
    if (t < m) sv[t] = vt / (sqrtf(s) + 1e-12f);
    __syncthreads();
    // wv = W v : warp-per-row, lane-strided coalesced reads + shuffle reduce
    int warp = t >> 5, lane = t & 31;
    for (int row = warp; row < n; row += 8) {
        float p = 0.f;
        for (int k = lane; k < m; k += 32) p += W[row * m + k] * sv[k];
#pragma unroll
        for (int mask = 16; mask > 0; mask >>= 1)
            p += __shfl_xor_sync(0xffffffffu, p, mask);
        if (lane == 0) swv[row] = p;
    }
    __syncthreads();
    float z = (t < n) ? swv[t] * swv[t] : 0.f;
    float s2 = block_reduce_sum256(z, sred);
    float sig = s2 / (sqrtf(s2) + 1e-12f);
    return 1.f / sig;
}

__global__ void setup_kernel(const long long* __restrict__ ei64, int N,
                             float* __restrict__ stats,
                             const float* __restrict__ W1, const float* __restrict__ u1,
                             const float* __restrict__ W2, const float* __restrict__ u2,
                             float* __restrict__ inv_sigma) {
    __shared__ float sv[128];
    __shared__ float swv[128];
    __shared__ float sred[256];
    __shared__ int sbad;
    int t = threadIdx.x;
    stats[t] = 0.f;
    if (t == 0) sbad = 0;
    __syncthreads();
    if (t < 64) {
        long long v = ei64[t];
        if (v < 0 || v >= (long long)N) atomicExch(&sbad, 1);
    }
    __syncthreads();
    if (t == 0) g_idx_mode = sbad;

    float is1 = inv_sigma_calc(W1, u1, NHID, NFEAT, sv, swv, sred);
    float is2 = inv_sigma_calc(W2, u2, NHID, NHID, sv, swv, sred);
    if (t == 0) { inv_sigma[0] = is1; inv_sigma[1] = is2; }
}

// ---------------- parallel W1 split ----------------
__global__ void wsplit1_kernel(const float* __restrict__ W1,
                               const float* __restrict__ inv_sigma,
                               ushort_t* __restrict__ w1hi, ushort_t* __restrict__ w1lo) {
    int i = blockIdx.x * blockDim.x + threadIdx.x;
    if (i >= NHID * NFEAT) return;
    float w = W1[i] * inv_sigma[0];
    ushort_t hi, lo;
    bsplit(w, hi, lo);
    w1hi[i] = hi;
    w1lo[i] = lo;
}

// ---------------- scatter: agg[dst] += x[src], vectorized red, 8 thr/edge ----------------
__global__ void scatter_kernel(const void* __restrict__ eiv,
                               const float4* __restrict__ x4,
                               float4* __restrict__ h4, int E, int N) {
    int i = blockIdx.x * blockDim.x + threadIdx.x;
    if (i >= E * 8) return;
    int e = i >> 3;
    int c = i & 7;
    long long s, d;
    if (g_idx_mode == 0) {
        const long long* ei = (const long long*)eiv;
        s = ei[e];
        d = ei[E + e];
    } else {
        const int* ei = (const int*)eiv;
        s = ei[e];
        d = ei[E + e];
    }
    if ((ull)s >= (ull)N || (ull)d >= (ull)N) return;  // safety: never IMA
    const float4* xs = x4 + s * 16 + c;
    float4 v0 = __ldg(xs);
    float4 v1 = __ldg(xs + 8);
    float4* p = h4 + d * 16 + c;
    asm volatile("red.global.add.v4.f32 [%0], {%1,%2,%3,%4};"
                 :: "l"(p), "f"(v0.x), "f"(v0.y), "f"(v0.z), "f"(v0.w) : "memory");
    asm volatile("red.global.add.v4.f32 [%0], {%1,%2,%3,%4};"
                 :: "l"(p + 8), "f"(v1.x), "f"(v1.y), "f"(v1.z), "f"(v1.w) : "memory");
}

// ---------------- tensor-core GEMM, compact hi/lo segments ----------------
// out[r][fcol0+f] = act( sum_k (in[r][k] (+x[r][k])) * W[fcol0+f][k] + bias )
// fp32 = bf16 3-term: hi*hi + lo_a*hi_b + hi_a*lo_b.
// 128 rows x NC cols per block, 512 threads.
template <int K, int NC, bool RELU, bool STATS, bool ADDX, int MINCTA>
__global__ void __launch_bounds__(512, MINCTA) gemm_kernel(
    const float* __restrict__ in, const float* __restrict__ xadd,
    const ushort_t* __restrict__ whi, const ushort_t* __restrict__ wlo,
    const float* __restrict__ bias, float* __restrict__ out,
    float* __restrict__ gstats) {
    constexpr int SAe = K + 8;
    constexpr int K4 = K / 4;
    constexpr int R8 = K / 8;
    constexpr int CW = NC / 32;            // col warps
    constexpr int MT = 128 / ((16 / CW) * 16);  // m16 tiles per warp (2 for NC=128, 1 for NC=64)
    constexpr int CB = 128 / NC;           // col blocks per row tile

    extern __shared__ ushort_t smu[];
    ushort_t* sAhi = smu;
    ushort_t* sAlo = sAhi + 128 * SAe;
    ushort_t* sBhi = sAlo + 128 * SAe;
    ushort_t* sBlo = sBhi + NC * SAe;
    float* sBias   = reinterpret_cast<float*>(sBlo + NC * SAe);
    float* sStats  = sBias + NC;

    const int tid = threadIdx.x;
    const int cb = blockIdx.x % CB;
    const int row0 = (blockIdx.x / CB) * 128;
    const int fcol0 = cb * NC;

    // B fill
    {
        const uint4* ghi = reinterpret_cast<const uint4*>(whi + (size_t)fcol0 * K);
        const uint4* glo = reinterpret_cast<const uint4*>(wlo + (size_t)fcol0 * K);
        for (int q = tid; q < NC * R8; q += 512) {
            int f = q / R8, c = q - f * R8;
            *reinterpret_cast<uint4*>(&sBhi[f * SAe + c * 8]) = ghi[q];
            *reinterpret_cast<uint4*>(&sBlo[f * SAe + c * 8]) = glo[q];
        }
    }
    // A fill: (in + x) -> bf16 hi/lo
    {
        const float4* in4 = reinterpret_cast<const float4*>(in);
        const float4* x4 = reinterpret_cast<const float4*>(xadd);
        for (int q = tid; q < 128 * K4; q += 512) {
            int r = q / K4, c = q - r * K4;
            size_t gi = (size_t)(row0 + r) * K4 + c;
            float4 v = in4[gi];
            if (ADDX) {
                float4 w = x4[gi];
                v.x += w.x; v.y += w.y; v.z += w.z; v.w += w.w;
            }
            ushort_t h0, l0, h1, l1, h2, l2, h3, l3;
            bsplit(v.x, h0, l0); bsplit(v.y, h1, l1);
            bsplit(v.z, h2, l2); bsplit(v.w, h3, l3);
            uint2 hw, lw;
            hw.x = pk(h0, h1); hw.y = pk(h2, h3);
            lw.x = pk(l0, l1); lw.y = pk(l2, l3);
            *reinterpret_cast<uint2*>(&sAhi[r * SAe + c * 4]) = hw;
            *reinterpret_cast<uint2*>(&sAlo[r * SAe + c * 4]) = lw;
        }
    }
    if (tid < NC) sBias[tid] = bias[fcol0 + tid];
    if (STATS && tid < 256) sStats[tid] = 0.f;
    __syncthreads();

    const int wid = tid >> 5;
    const int lane = tid & 31;
    const int g = lane >> 2;
    const int tg = lane & 3;
    const int rowBase = (wid / CW) * (MT * 16);
    const int colBase = (wid % CW) * 32;

    float acc[MT][4][4];
#pragma unroll
    for (int m = 0; m < MT; m++)
#pragma unroll
        for (int n = 0; n < 4; n++)
#pragma unroll
            for (int i = 0; i < 4; i++) acc[m][n][i] = 0.f;

    const int aoff = (rowBase + g) * SAe + tg * 2;
    const int boff = (colBase + g) * SAe + tg * 2;

#define MMA(ACC, A, B)                                                         \
    asm volatile(                                                              \
        "mma.sync.aligned.m16n8k16.row.col.f32.bf16.bf16.f32 "                 \
        "{%0,%1,%2,%3}, {%4,%5,%6,%7}, {%8,%9}, {%0,%1,%2,%3};"                \
        : "+f"((ACC)[0]), "+f"((ACC)[1]), "+f"((ACC)[2]), "+f"((ACC)[3])       \
        : "r"((A)[0]), "r"((A)[1]), "r"((A)[2]), "r"((A)[3]),                  \
          "r"((B)[0]), "r"((B)[1]))

#pragma unroll
    for (int kk = 0; kk < K / 16; kk++) {
        const int ko = kk * 16;
        unsigned ahi[MT][4], bhi[4][2];
#pragma unroll
        for (int m = 0; m < MT; m++) {
            int base = aoff + m * 16 * SAe + ko;
            ahi[m][0] = *reinterpret_cast<const unsigned*>(&sAhi[base]);
            ahi[m][1] = *reinterpret_cast<const unsigned*>(&sAhi[base + 8 * SAe]);
            ahi[m][2] = *reinterpret_cast<const unsigned*>(&sAhi[base + 8]);
            ahi[m][3] = *reinterpret_cast<const unsigned*>(&sAhi[base + 8 * SAe + 8]);
        }
#pragma unroll
        for (int n = 0; n < 4; n++) {
            int base = boff + n * 8 * SAe + ko;
            bhi[n][0] = *reinterpret_cast<const unsigned*>(&sBhi[base]);
            bhi[n][1] = *reinterpret_cast<const unsigned*>(&sBhi[base + 8]);
        }
#pragma unroll
        for (int m = 0; m < MT; m++)
#pragma unroll
            for (int n = 0; n < 4; n++) MMA(acc[m][n], ahi[m], bhi[n]);

        // seg: ahi x blo
        unsigned blo[4][2];
#pragma unroll
        for (int n = 0; n < 4; n++) {
            int base = boff + n * 8 * SAe + ko;
            blo[n][0] = *reinterpret_cast<const unsigned*>(&sBlo[base]);
            blo[n][1] = *reinterpret_cast<const unsigned*>(&sBlo[base + 8]);
        }
#pragma unroll
        for (int m = 0; m < MT; m++)
#pragma unroll
            for (int n = 0; n < 4; n++) MMA(acc[m][n], ahi[m], blo[n]);

        // seg: alo x bhi (bhi reused from registers)
        unsigned alo[MT][4];
#pragma unroll
        for (int m = 0; m < MT; m++) {
            int base = aoff + m * 16 * SAe + ko;
            alo[m][0] = *reinterpret_cast<const unsigned*>(&sAlo[base]);
            alo[m][1] = *reinterpret_cast<const unsigned*>(&sAlo[base + 8 * SAe]);
            alo[m][2] = *reinterpret_cast<const unsigned*>(&sAlo[base + 8]);
            alo[m][3] = *reinterpret_cast<const unsigned*>(&sAlo[base + 8 * SAe + 8]);
        }
#pragma unroll
        for (int m = 0; m < MT; m++)
#pragma unroll
            for (int n = 0; n < 4; n++) MMA(acc[m][n], alo[m], bhi[n]);
    }
#undef MMA

    // ---- epilogue ----
    float cs[4][2], css[4][2];
    if (STATS) {
#pragma unroll
        for (int n = 0; n < 4; n++) { cs[n][0] = cs[n][1] = css[n][0] = css[n][1] = 0.f; }
    }
#pragma unroll
    for (int m = 0; m < MT; m++) {
        int r = row0 + rowBase + m * 16 + g;
#pragma unroll
        for (int n = 0; n < 4; n++) {
            int f = colBase + n * 8 + tg * 2;
            float bx = sBias[f], by = sBias[f + 1];
            float2 o0 = make_float2(acc[m][n][0] + bx, acc[m][n][1] + by);
            float2 o1 = make_float2(acc[m][n][2] + bx, acc[m][n][3] + by);
            if (RELU) {
                o0.x = fmaxf(o0.x, 0.f); o0.y = fmaxf(o0.y, 0.f);
                o1.x = fmaxf(o1.x, 0.f); o1.y = fmaxf(o1.y, 0.f);
            }
            if (STATS) {
                cs[n][0] += o0.x + o1.x;  cs[n][1] += o0.y + o1.y;
                css[n][0] += o0.x * o0.x + o1.x * o1.x;
                css[n][1] += o0.y * o0.y + o1.y * o1.y;
            }
            *reinterpret_cast<float2*>(&out[(size_t)r * 128 + fcol0 + f]) = o0;
            *reinterpret_cast<float2*>(&out[(size_t)(r + 8) * 128 + fcol0 + f]) = o1;
        }
    }
    if (STATS) {
#pragma unroll
        for (int mask = 4; mask < 32; mask <<= 1) {
#pragma unroll
            for (int n = 0; n < 4; n++) {
#pragma unroll
                for (int j = 0; j < 2; j++) {
                    cs[n][j] += __shfl_xor_sync(0xffffffffu, cs[n][j], mask);
                    css[n][j] += __shfl_xor_sync(0xffffffffu, css[n][j], mask);
                }
            }
        }
        if (lane < 4) {
#pragma unroll
            for (int n = 0; n < 4; n++) {
#pragma unroll
                for (int j = 0; j < 2; j++) {
                    int f = colBase + n * 8 + lane * 2 + j;
                    atomicAdd(&sStats[f], cs[n][j]);
                    atomicAdd(&sStats[128 + f], css[n][j]);
                }
            }
        }
        __syncthreads();
        if (tid < 256) atomicAdd(&gstats[tid], sStats[tid]);
    }
}

// ---------------- parallel fold BN + SN into split W2eff / b2eff ----------------
__global__ void __launch_bounds__(128) finalize_kernel(
    const float* __restrict__ W2, const float* __restrict__ b2,
    const float* __restrict__ gamma, const float* __restrict__ beta,
    const float* __restrict__ stats, const float* __restrict__ inv_sigma,
    ushort_t* __restrict__ w2hi, ushort_t* __restrict__ w2lo,
    float* __restrict__ b2eff, int N) {
    const int t = blockIdx.x;   // output row
    const int f = threadIdx.x;  // input feature
    float invN = 1.f / (float)N;
    float mean = stats[f] * invN;
    float var = stats[128 + f] * invN - mean * mean;
    float af = gamma[f] * rsqrtf(var + 1e-5f);
    float cf = beta[f] - mean * af;

    float wsn = W2[t * 128 + f] * inv_sigma[1];
    float weff = wsn * af;
    ushort_t hi, lo;
    bsplit(weff, hi, lo);
    w2hi[t * 128 + f] = hi;
    w2lo[t * 128 + f] = lo;

    float v = cf * wsn;
#pragma unroll
    for (int mask = 16; mask > 0; mask >>= 1)
        v += __shfl_xor_sync(0xffffffffu, v, mask);
    __shared__ float sw[4];
    if ((f & 31) == 0) sw[f >> 5] = v;
    __syncthreads();
    if (f == 0) b2eff[t] = b2[t] + sw[0] + sw[1] + sw[2] + sw[3];
}

// ---------------- launch ----------------
extern "C" void kernel_launch(void* const* d_in, const int* in_sizes, int n_in,
                              void* d_out, int out_size) {
    const float* x        = (const float*)d_in[0];
    const void*  ei       = d_in[1];
    const float* W1       = (const float*)d_in[2];
    const float* b1       = (const float*)d_in[3];
    const float* u1       = (const float*)d_in[4];
    const float* gamma    = (const float*)d_in[5];
    const float* beta     = (const float*)d_in[6];
    const float* W2       = (const float*)d_in[7];
    const float* b2       = (const float*)d_in[8];
    const float* u2       = (const float*)d_in[9];

    int N = in_sizes[0] / NFEAT;
    int E = in_sizes[1] / 2;

    float *pAgg, *pH1, *pStats, *pInv, *pB2eff;
    ushort_t *pW1hi, *pW1lo, *pW2hi, *pW2lo;
    cudaGetSymbolAddress((void**)&pAgg, g_agg);
    cudaGetSymbolAddress((void**)&pH1, g_h1);
    cudaGetSymbolAddress((void**)&pStats, g_stats);
    cudaGetSymbolAddress((void**)&pInv, g_inv_sigma);
    cudaGetSymbolAddress((void**)&pB2eff, g_b2eff);
    cudaGetSymbolAddress((void**)&pW1hi, g_w1hi);
    cudaGetSymbolAddress((void**)&pW1lo, g_w1lo);
    cudaGetSymbolAddress((void**)&pW2hi, g_w2hi);
    cudaGetSymbolAddress((void**)&pW2lo, g_w2lo);

    // 1) setup: edge dtype probe + stats zero + spectral norms
    setup_kernel<<<1, 256>>>((const long long*)ei, N, pStats, W1, u1, W2, u2, pInv);

    // 1b) parallel W1 split
    wsplit1_kernel<<<(NHID * NFEAT + 255) / 256, 256>>>(W1, pInv, pW1hi, pW1lo);

    // 2) agg = 0
    cudaMemsetAsync(pAgg, 0, (size_t)N * NFEAT * sizeof(float));

    // 3) scatter-add agg[dst] += x[src]
    int items = E * 8;
    scatter_kernel<<<(items + 255) / 256, 256>>>(ei, (const float4*)x, (float4*)pAgg, E, N);

    // 4) h1 = relu((agg + x) @ (W1/s1)^T + b1), fused BN-stats
    {
        constexpr int SAe = NFEAT + 8;
        int smem = (2 * 128 + 2 * 128) * SAe * 2 + (128 + 256) * 4;
        cudaFuncSetAttribute((const void*)gemm_kernel<NFEAT, 128, true, true, true, 2>,
                             cudaFuncAttributeMaxDynamicSharedMemorySize, smem);
        gemm_kernel<NFEAT, 128, true, true, true, 2><<<N / 128, 512, smem>>>(
            pAgg, x, pW1hi, pW1lo, b1, pH1, pStats);
    }

    // 5) parallel fold BN+SN into split W2eff / b2eff
    finalize_kernel<<<128, 128>>>(W2, b2, gamma, beta, pStats, pInv, pW2hi, pW2lo, pB2eff, N);

    // 6) out = h1 @ W2eff^T + b2eff  (split-N: 128x64 tiles, 2 CTA/SM)
    {
        constexpr int SAe = NHID + 8;
        int smem = (2 * 128 + 2 * 64) * SAe * 2 + (64 + 256) * 4;
        cudaFuncSetAttribute((const void*)gemm_kernel<NHID, 64, false, false, false, 2>,
                             cudaFuncAttributeMaxDynamicSharedMemorySize, smem);
        gemm_kernel<NHID, 64, false, false, false, 2><<<(N / 128) * 2, 512, smem>>>(
            pH1, nullptr, pW2hi, pW2lo, pB2eff, (float*)d_out, nullptr);
    }
}